// round 13
// baseline (speedup 1.0000x reference)
#include <cuda_runtime.h>
#include <math.h>
#include <stdint.h>

#define HEADS 8
#define DH    64
#define DIM   512
#define QKVD  1536
#define NTOK  15130
#define NPAD  15360
#define PADR  230
#define NL    256
#define LCH   60
#define IMGH  123
#define NPIX  15129
#define NSPLIT 16
#define PBLOCKS 128

// ---------------- static scratch (allocation-free rule) ----------------
__device__ __align__(16) float g_h   [NTOK*DIM];
__device__ __align__(16) float g_xln [NPAD*DIM];
__device__ __align__(16) float g_qkv [NPAD*3*DIM];
__device__ __align__(16) float g_QL  [HEADS*NL*DH];
__device__ __align__(16) float g_KL  [HEADS*NL*DH];
__device__ __align__(16) float g_A3  [HEADS*NL*NPAD];
__device__ __align__(16) float g_S2  [HEADS*NL*NL];
__device__ __align__(16) float g_XZ  [HEADS*NL*NL];
__device__ __align__(16) float g_T1  [HEADS*NL*NL];
__device__ __align__(16) float g_T2  [HEADS*NL*NL];
__device__ __align__(16) float g_Zb  [HEADS*NL*NL];
__device__ __align__(16) float g_Z2b [HEADS*NL*NL];
__device__ __align__(16) float g_Tb  [HEADS*NL*DH];
__device__ __align__(16) float g_Ub  [HEADS*NL*DH];
__device__ __align__(16) float g_attn[NPAD*DIM];
__device__ __align__(16) float g_y   [NPAD*DIM];
__device__ float g_scal[2];
__device__ unsigned g_bar_cnt = 0;
__device__ volatile unsigned g_bar_gen = 0;
__device__ unsigned g_hbar_cnt[HEADS];
__device__ volatile unsigned g_hbar_gen[HEADS];

// ================= bf16 split primitives =================
__device__ __forceinline__ uint32_t pkbf(float x0, float x1) {
    uint32_t r;
    asm("cvt.rn.bf16x2.f32 %0, %1, %2;" : "=r"(r) : "f"(x1), "f"(x0));
    return r;
}
__device__ __forceinline__ float unlo(uint32_t p) {
    return __uint_as_float(p << 16);
}
__device__ __forceinline__ float unhi(uint32_t p) {
    return __uint_as_float(p & 0xFFFF0000u);
}
__device__ __forceinline__ void bsplit4(float4 v,
    uint32_t& h0, uint32_t& h1, uint32_t& l0, uint32_t& l1)
{
    h0 = pkbf(v.x, v.y);
    h1 = pkbf(v.z, v.w);
    l0 = pkbf(v.x - unlo(h0), v.y - unhi(h0));
    l1 = pkbf(v.z - unlo(h1), v.w - unhi(h1));
}
__device__ __forceinline__ void bsplit2(float x0, float x1, uint32_t& h, uint32_t& l) {
    h = pkbf(x0, x1);
    l = pkbf(x0 - unlo(h), x1 - unhi(h));
}
__device__ __forceinline__ void mma16(float* d,
    uint32_t a0, uint32_t a1, uint32_t a2, uint32_t a3,
    uint32_t b0, uint32_t b1)
{
    asm volatile("mma.sync.aligned.m16n8k16.row.col.f32.bf16.bf16.f32 "
        "{%0,%1,%2,%3},{%4,%5,%6,%7},{%8,%9},{%0,%1,%2,%3};"
        : "+f"(d[0]), "+f"(d[1]), "+f"(d[2]), "+f"(d[3])
        : "r"(a0), "r"(a1), "r"(a2), "r"(a3), "r"(b0), "r"(b1));
}
__device__ __forceinline__ void mma16_split(float* acc,
    const uint32_t* Ah, const uint32_t* Al, const uint32_t* Bh, const uint32_t* Bl)
{
    mma16(acc, Ah[0],Ah[1],Ah[2],Ah[3], Bh[0],Bh[1]);
    mma16(acc, Ah[0],Ah[1],Ah[2],Ah[3], Bl[0],Bl[1]);
    mma16(acc, Al[0],Al[1],Al[2],Al[3], Bh[0],Bh[1]);
}

#define PADS 4

// ================= generic bf16-split GEMM (batched, NN/NT, split-K) ============
// (R9-verified layout: k-pair-major packed tiles, scalar fragment LDS)
template<int BM, int BN, int WM, int WN, bool NT, bool SPLITK>
__global__ void __launch_bounds__((BM/WM)*(BN/WN)*32)
gemm_mma(const float* __restrict__ A, const float* __restrict__ B,
         float* __restrict__ C,
         int M, int N, int K, int lda, int ldb, int ldc,
         long sA, long sB, long sC,
         float alpha, float beta_diag, float gammaA,
         const float* __restrict__ bias, int mode)
{
    constexpr int NWARP = (BM/WM)*(BN/WN);
    constexpr int T = NWARP * 32;
    constexpr int NWN = BN / WN;
    constexpr int MT = WM / 16, NTL = WN / 8;
    static_assert(T == 8 * (BN / 4), "B-NN loader mapping requires T == 2*BN");

    int z = blockIdx.z;
    int kbeg = 0, kend = K;
    if (SPLITK) {
        int batch = z / NSPLIT, split = z % NSPLIT;
        A += (long)batch * sA; B += (long)batch * sB; C += (long)batch * sC;
        int chunk = K / NSPLIT;
        kbeg = split * chunk; kend = kbeg + chunk;
    } else {
        A += (long)z * sA; B += (long)z * sB; C += (long)z * sC;
    }

    __shared__ __align__(16) uint32_t sAh[2][8][BM + PADS];
    __shared__ __align__(16) uint32_t sAl[2][8][BM + PADS];
    __shared__ __align__(16) uint32_t sBh[2][8][BN + PADS];
    __shared__ __align__(16) uint32_t sBl[2][8][BN + PADS];

    const int tid = threadIdx.x;
    const int wid = tid >> 5, lane = tid & 31;
    const int g = lane >> 2, t = lane & 3;
    const int row0 = blockIdx.y * BM;
    const int col0 = blockIdx.x * BN;
    const int wm0 = (wid / NWN) * WM;
    const int wn0 = (wid % NWN) * WN;

    float4 ra[2], rb[2];

    auto load_g = [&](int k0) {
        #pragma unroll
        for (int it = 0; it < 2; it++) {
            int i = tid + it * T;
            int m = i >> 2, kq = (i & 3) * 4;
            int gm = row0 + m;
            ra[it] = make_float4(0.f, 0.f, 0.f, 0.f);
            if (gm < M) ra[it] = *(const float4*)&A[(long)gm * lda + k0 + kq];
        }
        if (!NT) {
            int k2 = tid / (BN / 4), ng = (tid % (BN / 4)) * 4;
            rb[0] = *(const float4*)&B[(long)(k0 + 2*k2)     * ldb + col0 + ng];
            rb[1] = *(const float4*)&B[(long)(k0 + 2*k2 + 1) * ldb + col0 + ng];
        } else {
            #pragma unroll
            for (int it = 0; it < 2; it++) {
                int i = tid + it * T;
                int n = i >> 2, kq = (i & 3) * 4;
                rb[it] = make_float4(0.f, 0.f, 0.f, 0.f);
                if (col0 + n < N)
                    rb[it] = *(const float4*)&B[(long)(col0 + n) * ldb + k0 + kq];
            }
        }
    };
    auto store_s = [&](int buf) {
        #pragma unroll
        for (int it = 0; it < 2; it++) {
            int i = tid + it * T;
            int m = i >> 2, kp = (i & 3) * 2;
            uint32_t h0, h1, l0, l1;
            bsplit4(ra[it], h0, h1, l0, l1);
            sAh[buf][kp][m]     = h0;
            sAh[buf][kp + 1][m] = h1;
            sAl[buf][kp][m]     = l0;
            sAl[buf][kp + 1][m] = l1;
        }
        if (!NT) {
            int k2 = tid / (BN / 4), ng = (tid % (BN / 4)) * 4;
            const float* v0 = &rb[0].x;
            const float* v1 = &rb[1].x;
            uint32_t hh[4], ll[4];
            #pragma unroll
            for (int q = 0; q < 4; q++) {
                uint32_t h = pkbf(v0[q], v1[q]);
                hh[q] = h;
                ll[q] = pkbf(v0[q] - unlo(h), v1[q] - unhi(h));
            }
            *(uint4*)&sBh[buf][k2][ng] = *(uint4*)hh;
            *(uint4*)&sBl[buf][k2][ng] = *(uint4*)ll;
        } else {
            #pragma unroll
            for (int it = 0; it < 2; it++) {
                int i = tid + it * T;
                int n = i >> 2, kp = (i & 3) * 2;
                uint32_t h0, h1, l0, l1;
                bsplit4(rb[it], h0, h1, l0, l1);
                sBh[buf][kp][n]     = h0;
                sBh[buf][kp + 1][n] = h1;
                sBl[buf][kp][n]     = l0;
                sBl[buf][kp + 1][n] = l1;
            }
        }
    };

    float acc[MT][NTL][4];
    #pragma unroll
    for (int i = 0; i < MT; i++)
        #pragma unroll
        for (int j = 0; j < NTL; j++)
            #pragma unroll
            for (int q = 0; q < 4; q++) acc[i][j][q] = 0.f;

    const int ntiles = (kend - kbeg) / 16;
    load_g(kbeg);
    store_s(0);
    __syncthreads();

    for (int kt = 0; kt < ntiles; kt++) {
        if (kt + 1 < ntiles) load_g(kbeg + (kt + 1) * 16);
        int buf = kt & 1;
        {
            uint32_t Ahf[MT][4], Alf[MT][4], Bhf[NTL][2], Blf[NTL][2];
            #pragma unroll
            for (int mt = 0; mt < MT; mt++) {
                int mb = wm0 + mt * 16 + g;
                Ahf[mt][0] = sAh[buf][t    ][mb];
                Ahf[mt][1] = sAh[buf][t    ][mb + 8];
                Ahf[mt][2] = sAh[buf][t + 4][mb];
                Ahf[mt][3] = sAh[buf][t + 4][mb + 8];
                Alf[mt][0] = sAl[buf][t    ][mb];
                Alf[mt][1] = sAl[buf][t    ][mb + 8];
                Alf[mt][2] = sAl[buf][t + 4][mb];
                Alf[mt][3] = sAl[buf][t + 4][mb + 8];
            }
            #pragma unroll
            for (int nt = 0; nt < NTL; nt++) {
                int nb = wn0 + nt * 8 + g;
                Bhf[nt][0] = sBh[buf][t    ][nb];
                Bhf[nt][1] = sBh[buf][t + 4][nb];
                Blf[nt][0] = sBl[buf][t    ][nb];
                Blf[nt][1] = sBl[buf][t + 4][nb];
            }
            #pragma unroll
            for (int mt = 0; mt < MT; mt++)
                #pragma unroll
                for (int nt = 0; nt < NTL; nt++)
                    mma16_split(acc[mt][nt], Ahf[mt], Alf[mt], Bhf[nt], Blf[nt]);
        }
        if (kt + 1 < ntiles) {
            store_s((kt + 1) & 1);
            __syncthreads();
        }
    }

    auto emit = [&](int r, int c, float v0, float v1) {
        if (r >= M) return;
        v0 *= alpha; v1 *= alpha;
        if (bias) { v0 += bias[c]; v1 += bias[c + 1]; }
        if (beta_diag != 0.f) {
            if (r == c)     v0 += beta_diag;
            if (r == c + 1) v1 += beta_diag;
        }
        if (gammaA != 0.f) {
            v0 += gammaA * A[(long)r * lda + c];
            v1 += gammaA * A[(long)r * lda + c + 1];
        }
        if (mode == 1) { v0 = fmaxf(v0, 0.f); v1 = fmaxf(v1, 0.f); }
        if (SPLITK) {
            atomicAdd(&C[(long)r * ldc + c], v0);
            atomicAdd(&C[(long)r * ldc + c + 1], v1);
        } else if (mode == 2) {
            if (r >= PADR) {
                float2* dst = (float2*)&C[(long)(r - PADR) * ldc + c];
                float2 o = *dst;
                o.x += v0; o.y += v1;
                *dst = o;
            }
        } else {
            *(float2*)&C[(long)r * ldc + c] = make_float2(v0, v1);
        }
    };
    #pragma unroll
    for (int mt = 0; mt < MT; mt++)
        #pragma unroll
        for (int nt = 0; nt < NTL; nt++) {
            int r = row0 + wm0 + mt * 16 + g;
            int c = col0 + wn0 + nt * 8 + 2 * t;
            emit(r,     c, acc[mt][nt][0], acc[mt][nt][1]);
            emit(r + 8, c, acc[mt][nt][2], acc[mt][nt][3]);
        }
}

// ================= persistent pinv kernel (bf16 split, per-head barriers) =======
__device__ __forceinline__ void atomicMaxFloatPos(float* addr, float v) {
    atomicMax((int*)addr, __float_as_int(v));
}

__device__ __forceinline__ void gridbar() {
    __syncthreads();
    if (threadIdx.x == 0) {
        unsigned gen = g_bar_gen;
        __threadfence();
        if (atomicAdd(&g_bar_cnt, 1u) == PBLOCKS - 1) {
            g_bar_cnt = 0;
            __threadfence();
            g_bar_gen = gen + 1;
        } else {
            while (g_bar_gen == gen) { __nanosleep(64); }
        }
        __threadfence();
    }
    __syncthreads();
}

__device__ __forceinline__ void headbar(int head) {
    __syncthreads();
    if (threadIdx.x == 0) {
        unsigned gen = g_hbar_gen[head];
        __threadfence();
        if (atomicAdd(&g_hbar_cnt[head], 1u) == 15) {
            g_hbar_cnt[head] = 0;
            __threadfence();
            g_hbar_gen[head] = gen + 1;
        } else {
            while (g_hbar_gen[head] == gen) { __nanosleep(32); }
        }
        __threadfence();
    }
    __syncthreads();
}

typedef uint32_t pktile[2][8][68];

__device__ __noinline__ void gemm64_dev(
    const float* __restrict__ A, const float* __restrict__ B, float* __restrict__ C,
    int row0, int col0, float alpha, float beta_diag, float gammaA,
    pktile& Ah, pktile& Al, pktile& Bh, pktile& Bl)
{
    const int tid = threadIdx.x;
    const int wid = tid >> 5, lane = tid & 31;
    const int g = lane >> 2, t = lane & 3;
    const int wm0 = (wid >> 1) * 32, wn0 = (wid & 1) * 32;

    float4 ra[2], rb0, rb1;
    const int k2 = tid >> 4, ng = (tid & 15) * 4;

    auto load_g = [&](int k0) {
        #pragma unroll
        for (int it = 0; it < 2; it++) {
            int i = tid + it * 128;
            int m = i >> 2, kq = (i & 3) * 4;
            ra[it] = *(const float4*)&A[(long)(row0 + m) * 256 + k0 + kq];
        }
        rb0 = *(const float4*)&B[(long)(k0 + 2*k2)     * 256 + col0 + ng];
        rb1 = *(const float4*)&B[(long)(k0 + 2*k2 + 1) * 256 + col0 + ng];
    };
    auto store_s = [&](int buf) {
        #pragma unroll
        for (int it = 0; it < 2; it++) {
            int i = tid + it * 128;
            int m = i >> 2, kp = (i & 3) * 2;
            uint32_t h0, h1, l0, l1;
            bsplit4(ra[it], h0, h1, l0, l1);
            Ah[buf][kp][m]     = h0;
            Ah[buf][kp + 1][m] = h1;
            Al[buf][kp][m]     = l0;
            Al[buf][kp + 1][m] = l1;
        }
        const float* v0 = &rb0.x;
        const float* v1 = &rb1.x;
        uint32_t hh[4], ll[4];
        #pragma unroll
        for (int q = 0; q < 4; q++) {
            uint32_t h = pkbf(v0[q], v1[q]);
            hh[q] = h;
            ll[q] = pkbf(v0[q] - unlo(h), v1[q] - unhi(h));
        }
        *(uint4*)&Bh[buf][k2][ng] = *(uint4*)hh;
        *(uint4*)&Bl[buf][k2][ng] = *(uint4*)ll;
    };

    float acc[2][4][4] = {};
    load_g(0);
    store_s(0);
    __syncthreads();
    for (int kt = 0; kt < 16; kt++) {
        if (kt + 1 < 16) load_g((kt + 1) * 16);
        int buf = kt & 1;
        {
            uint32_t Ahf[2][4], Alf[2][4], Bhf[4][2], Blf[4][2];
            #pragma unroll
            for (int mt = 0; mt < 2; mt++) {
                int mb = wm0 + mt * 16 + g;
                Ahf[mt][0] = Ah[buf][t    ][mb];
                Ahf[mt][1] = Ah[buf][t    ][mb + 8];
                Ahf[mt][2] = Ah[buf][t + 4][mb];
                Ahf[mt][3] = Ah[buf][t + 4][mb + 8];
                Alf[mt][0] = Al[buf][t    ][mb];
                Alf[mt][1] = Al[buf][t    ][mb + 8];
                Alf[mt][2] = Al[buf][t + 4][mb];
                Alf[mt][3] = Al[buf][t + 4][mb + 8];
            }
            #pragma unroll
            for (int nt = 0; nt < 4; nt++) {
                int nb = wn0 + nt * 8 + g;
                Bhf[nt][0] = Bh[buf][t    ][nb];
                Bhf[nt][1] = Bh[buf][t + 4][nb];
                Blf[nt][0] = Bl[buf][t    ][nb];
                Blf[nt][1] = Bl[buf][t + 4][nb];
            }
            #pragma unroll
            for (int mt = 0; mt < 2; mt++)
                #pragma unroll
                for (int nt = 0; nt < 4; nt++)
                    mma16_split(acc[mt][nt], Ahf[mt], Alf[mt], Bhf[nt], Blf[nt]);
        }
        if (kt + 1 < 16) {
            store_s((kt + 1) & 1);
            __syncthreads();
        }
    }
    #pragma unroll
    for (int mt = 0; mt < 2; mt++)
        #pragma unroll
        for (int nt = 0; nt < 4; nt++) {
            int r0 = row0 + wm0 + mt * 16 + g;
            int c = col0 + wn0 + nt * 8 + 2 * t;
            #pragma unroll
            for (int half = 0; half < 2; half++) {
                int r = r0 + half * 8;
                float v0 = alpha * acc[mt][nt][half*2 + 0];
                float v1 = alpha * acc[mt][nt][half*2 + 1];
                if (beta_diag != 0.f) {
                    if (r == c)     v0 += beta_diag;
                    if (r == c + 1) v1 += beta_diag;
                }
                if (gammaA != 0.f) {
                    v0 += gammaA * A[(long)r * 256 + c];
                    v1 += gammaA * A[(long)r * 256 + c + 1];
                }
                *(float2*)&C[(long)r * 256 + c] = make_float2(v0, v1);
            }
        }
    __syncthreads();
}

__global__ void __launch_bounds__(128) pinv_persist(
    const float* __restrict__ S2, float* __restrict__ Z, float* __restrict__ Z2,
    float* __restrict__ XZ, float* __restrict__ T1, float* __restrict__ T2,
    float* __restrict__ scal)
{
    __shared__ __align__(16) uint32_t Ah[2][8][68], Al[2][8][68];
    __shared__ __align__(16) uint32_t Bh[2][8][68], Bl[2][8][68];
    const int b = blockIdx.x, tid = threadIdx.x;
    const int wid = tid >> 5, lane = tid & 31;

    if (b == 0 && tid < 2) scal[tid] = 0.f;
    gridbar();

    for (int q = 0; q < 8; q++) {
        int idx = b * 32 + wid * 8 + q;
        int mode = idx >> 11, rem = idx & 2047;
        int h = rem >> 8, i = rem & 255;
        const float* base = S2 + (long)h * 65536;
        float s = 0.f;
        if (mode == 0) { for (int j = lane; j < 256; j += 32) s += fabsf(base[i * 256 + j]); }
        else           { for (int j = lane; j < 256; j += 32) s += fabsf(base[j * 256 + i]); }
        #pragma unroll
        for (int o = 16; o; o >>= 1) s += __shfl_xor_sync(~0u, s, o);
        if (lane == 0) atomicMaxFloatPos(&scal[mode], s);
    }
    gridbar();

    float denom = scal[0] * scal[1];
    for (int l = 0; l < 32; l++) {
        int idx = b * 4096 + l * 128 + tid;
        int h = idx >> 16, rc = idx & 65535, r = rc >> 8, c = rc & 255;
        Z[idx] = S2[(long)h * 65536 + (long)c * 256 + r] / denom;
    }
    gridbar();

    const int head = b >> 4, tt = b & 15;
    const int row0 = (tt >> 2) * 64, col0 = (tt & 3) * 64;
    const long ho = (long)head * 65536;

    for (int it = 0; it < 6; it++) {
        float* zin  = (it & 1) ? Z2 : Z;
        float* zout = (it & 1) ? Z  : Z2;
        gemm64_dev(S2 + ho, zin + ho, XZ + ho, row0, col0, 1.f, 0.f, 0.f, Ah, Al, Bh, Bl);
        headbar(head);
        gemm64_dev(XZ + ho, XZ + ho, T2 + ho, row0, col0, 1.f, 15.f, -7.f, Ah, Al, Bh, Bl);
        headbar(head);
        gemm64_dev(XZ + ho, T2 + ho, T1 + ho, row0, col0, -1.f, 13.f, 0.f, Ah, Al, Bh, Bl);
        headbar(head);
        gemm64_dev(zin + ho, T1 + ho, zout + ho, row0, col0, 0.25f, 0.f, 0.f, Ah, Al, Bh, Bl);
        headbar(head);
    }
}

// ================= fused a1 attention (bf16 split): attn += softmax(P)@U ========
#define A1_AQH   0
#define A1_AQL   (32*68)
#define A1_BKH   (2*32*68)
#define A1_BKL   (2*32*68 + 32*260)
#define A1_PH    0
#define A1_PL    (128*68)
#define A1_ST    20992
#define A1_UH    37632
#define A1_UL    (37632 + 128*68)
#define A1_RINV  55040
#define A1_SMEMB (55104*4)

__global__ void __launch_bounds__(128) attn1_fused(
    const float* __restrict__ qkv, const float* __restrict__ KL,
    const float* __restrict__ U, float* __restrict__ attn)
{
    extern __shared__ float sm[];
    uint32_t* AQh = (uint32_t*)sm + A1_AQH;
    uint32_t* AQl = (uint32_t*)sm + A1_AQL;
    uint32_t* BKh = (uint32_t*)sm + A1_BKH;
    uint32_t* BKl = (uint32_t*)sm + A1_BKL;
    uint32_t* Ph  = (uint32_t*)sm + A1_PH;
    uint32_t* Pl  = (uint32_t*)sm + A1_PL;
    float*    ST  = sm + A1_ST;
    uint32_t* Uh  = (uint32_t*)sm + A1_UH;
    uint32_t* Ul  = (uint32_t*)sm + A1_UL;
    float*    rinv= sm + A1_RINV;

    const int tid = threadIdx.x;
    const int wid = tid >> 5, lane = tid & 31;
    const int g = lane >> 2, t = lane & 3;
    const int h = blockIdx.y;
    const int row0 = blockIdx.x * 64;
    const float* Qg  = qkv + h * DH;
    const float* KLh = KL + (long)h * NL * DH;
    const float* Ug  = U  + (long)h * NL * DH;

    #pragma unroll
    for (int l = 0; l < 8; l++) {
        int i = tid + l * 128;
        int m = i >> 4, kq = (i & 15) * 4;
        float4 v = *(const float4*)&Qg[(long)(row0 + m) * QKVD + kq];
        uint32_t h0, h1, l0, l1;
        bsplit4(v, h0, h1, l0, l1);
        int kp = kq >> 1;
        AQh[kp*68 + m] = h0; AQh[(kp+1)*68 + m] = h1;
        AQl[kp*68 + m] = l0; AQl[(kp+1)*68 + m] = l1;
    }
    #pragma unroll
    for (int l = 0; l < 32; l++) {
        int i = tid + l * 128;
        int n = i >> 4, kq = (i & 15) * 4;
        float4 v = *(const float4*)&KLh[n * 64 + kq];
        uint32_t h0, h1, l0, l1;
        bsplit4(v, h0, h1, l0, l1);
        int kp = kq >> 1;
        BKh[kp*260 + n] = h0; BKh[(kp+1)*260 + n] = h1;
        BKl[kp*260 + n] = l0; BKl[(kp+1)*260 + n] = l1;
    }
    #pragma unroll
    for (int l = 0; l < 16; l++) {
        int i = tid + l * 128;
        int kp = i >> 4, n4 = (i & 15) * 4;
        float4 v0 = *(const float4*)&Ug[(long)(2*kp)     * 64 + n4];
        float4 v1 = *(const float4*)&Ug[(long)(2*kp + 1) * 64 + n4];
        const float* p0 = &v0.x;
        const float* p1 = &v1.x;
        uint32_t hh[4], ll[4];
        #pragma unroll
        for (int q = 0; q < 4; q++) {
            uint32_t hq = pkbf(p0[q], p1[q]);
            hh[q] = hq;
            ll[q] = pkbf(p0[q] - unlo(hq), p1[q] - unhi(hq));
        }
        *(uint4*)&Uh[kp*68 + n4] = *(uint4*)hh;
        *(uint4*)&Ul[kp*68 + n4] = *(uint4*)ll;
    }
    __syncthreads();

    const int wm0 = (wid >> 1) * 32;
    const int wn1 = (wid & 1) * 128;
    {
        float acc1[2][16][4] = {};
        #pragma unroll
        for (int k16 = 0; k16 < 4; k16++) {
            int kb = k16 * 8;
            uint32_t Ahf[2][4], Alf[2][4];
            #pragma unroll
            for (int mt = 0; mt < 2; mt++) {
                int mb = wm0 + mt * 16 + g;
                Ahf[mt][0] = AQh[(kb + t    )*68 + mb];
                Ahf[mt][1] = AQh[(kb + t    )*68 + mb + 8];
                Ahf[mt][2] = AQh[(kb + t + 4)*68 + mb];
                Ahf[mt][3] = AQh[(kb + t + 4)*68 + mb + 8];
                Alf[mt][0] = AQl[(kb + t    )*68 + mb];
                Alf[mt][1] = AQl[(kb + t    )*68 + mb + 8];
                Alf[mt][2] = AQl[(kb + t + 4)*68 + mb];
                Alf[mt][3] = AQl[(kb + t + 4)*68 + mb + 8];
            }
            #pragma unroll
            for (int nt = 0; nt < 16; nt++) {
                int nb = wn1 + nt * 8 + g;
                uint32_t Bhf[2], Blf[2];
                Bhf[0] = BKh[(kb + t    )*260 + nb];
                Bhf[1] = BKh[(kb + t + 4)*260 + nb];
                Blf[0] = BKl[(kb + t    )*260 + nb];
                Blf[1] = BKl[(kb + t + 4)*260 + nb];
                mma16_split(acc1[0][nt], Ahf[0], Alf[0], Bhf, Blf);
                mma16_split(acc1[1][nt], Ahf[1], Alf[1], Bhf, Blf);
            }
        }
        #pragma unroll
        for (int mt = 0; mt < 2; mt++)
            #pragma unroll
            for (int nt = 0; nt < 16; nt++) {
                int r = wm0 + mt * 16 + g;
                int c = wn1 + nt * 8 + 2 * t;
                ST[c*65 + r]       = 0.125f * acc1[mt][nt][0];
                ST[(c+1)*65 + r]   = 0.125f * acc1[mt][nt][1];
                ST[c*65 + r+8]     = 0.125f * acc1[mt][nt][2];
                ST[(c+1)*65 + r+8] = 0.125f * acc1[mt][nt][3];
            }
    }
    __syncthreads();

    {
        int r = tid >> 1, half = tid & 1;
        int j0 = half * 128;
        float m = -1e30f;
        #pragma unroll 8
        for (int j = j0; j < j0 + 128; j++) m = fmaxf(m, ST[j*65 + r]);
        m = fmaxf(m, __shfl_xor_sync(~0u, m, 1));
        float s = 0.f;
        #pragma unroll 8
        for (int j = j0; j < j0 + 128; j++) {
            float e = __expf(ST[j*65 + r] - m);
            ST[j*65 + r] = e;
            s += e;
        }
        s += __shfl_xor_sync(~0u, s, 1);
        if (half == 0) rinv[r] = 1.f / s;
    }
    __syncthreads();

    #pragma unroll
    for (int l = 0; l < 64; l++) {
        int i = tid + l * 128;
        int kp = i >> 6, m = i & 63;
        float x0 = ST[(2*kp)     * 65 + m];
        float x1 = ST[(2*kp + 1) * 65 + m];
        uint32_t hq, lq;
        bsplit2(x0, x1, hq, lq);
        Ph[kp*68 + m] = hq;
        Pl[kp*68 + m] = lq;
    }
    __syncthreads();

    {
        const int wn2 = (wid & 1) * 32;
        float acc2[2][4][4] = {};
        #pragma unroll 4
        for (int k16 = 0; k16 < 16; k16++) {
            int kb = k16 * 8;
            uint32_t Ahf[2][4], Alf[2][4], Bhf[4][2], Blf[4][2];
            #pragma unroll
            for (int mt = 0; mt < 2; mt++) {
                int mb = wm0 + mt * 16 + g;
                Ahf[mt][0] = Ph[(kb + t    )*68 + mb];
                Ahf[mt][1] = Ph[(kb + t    )*68 + mb + 8];
                Ahf[mt][2] = Ph[(kb + t + 4)*68 + mb];
                Ahf[mt][3] = Ph[(kb + t + 4)*68 + mb + 8];
                Alf[mt][0] = Pl[(kb + t    )*68 + mb];
                Alf[mt][1] = Pl[(kb + t    )*68 + mb + 8];
                Alf[mt][2] = Pl[(kb + t + 4)*68 + mb];
                Alf[mt][3] = Pl[(kb + t + 4)*68 + mb + 8];
            }
            #pragma unroll
            for (int nt = 0; nt < 4; nt++) {
                int nb = wn2 + nt * 8 + g;
                Bhf[nt][0] = Uh[(kb + t    )*68 + nb];
                Bhf[nt][1] = Uh[(kb + t + 4)*68 + nb];
                Blf[nt][0] = Ul[(kb + t    )*68 + nb];
                Blf[nt][1] = Ul[(kb + t + 4)*68 + nb];
            }
            #pragma unroll
            for (int mt = 0; mt < 2; mt++)
                #pragma unroll
                for (int nt = 0; nt < 4; nt++)
                    mma16_split(acc2[mt][nt], Ahf[mt], Alf[mt], Bhf[nt], Blf[nt]);
        }
        #pragma unroll
        for (int mt = 0; mt < 2; mt++)
            #pragma unroll
            for (int nt = 0; nt < 4; nt++) {
                int rl = wm0 + mt * 16 + g;
                int c = h * DH + wn2 + nt * 8 + 2 * t;
                float i0 = rinv[rl], i1 = rinv[rl + 8];
                float2* d0 = (float2*)&attn[(long)(row0 + rl) * DIM + c];
                float2 o0 = *d0;
                o0.x += acc2[mt][nt][0] * i0;
                o0.y += acc2[mt][nt][1] * i0;
                *d0 = o0;
                float2* d1 = (float2*)&attn[(long)(row0 + rl + 8) * DIM + c];
                float2 o1 = *d1;
                o1.x += acc2[mt][nt][2] * i1;
                o1.y += acc2[mt][nt][3] * i1;
                *d1 = o1;
            }
    }
}

// ---------------- misc kernels ----------------
__global__ void zero_kernel(float* p, long n) {
    long i = (long)blockIdx.x * blockDim.x + threadIdx.x;
    if (i < n) p[i] = 0.f;
}

__global__ void set_cls(float* h, const float* __restrict__ cls) {
    h[threadIdx.x] = cls[threadIdx.x];
}

__global__ void dup_rows(float* h) {
    int i = blockIdx.x * blockDim.x + threadIdx.x;
    if (i < 129*DIM) {
        int t = i / DIM, c = i % DIM;
        h[(long)(15001 + t)*DIM + c] = h[(long)(1 + t)*DIM + c];
    }
}

__global__ void __launch_bounds__(256) ln_pad(
    const float* __restrict__ h, float* __restrict__ xo,
    const float* __restrict__ g, const float* __restrict__ b)
{
    int row = blockIdx.x, tid = threadIdx.x;
    float2* out2 = (float2*)(xo + (long)row * DIM);
    if (row < PADR) { out2[tid] = make_float2(0.f, 0.f); return; }
    const float2 xv = ((const float2*)(h + (long)(row - PADR) * DIM))[tid];
    __shared__ float sm1[8], sm2[8];
    float s = xv.x + xv.y;
    #pragma unroll
    for (int o = 16; o; o >>= 1) s += __shfl_xor_sync(~0u, s, o);
    if ((tid & 31) == 0) sm1[tid >> 5] = s;
    __syncthreads();
    float mu = (sm1[0]+sm1[1]+sm1[2]+sm1[3]+sm1[4]+sm1[5]+sm1[6]+sm1[7]) * (1.f/DIM);
    float d0 = xv.x - mu, d1 = xv.y - mu;
    float v = d0*d0 + d1*d1;
    #pragma unroll
    for (int o = 16; o; o >>= 1) v += __shfl_xor_sync(~0u, v, o);
    if ((tid & 31) == 0) sm2[tid >> 5] = v;
    __syncthreads();
    float var = (sm2[0]+sm2[1]+sm2[2]+sm2[3]+sm2[4]+sm2[5]+sm2[6]+sm2[7]) * (1.f/DIM);
    float rstd = rsqrtf(var + 1e-5f);
    float2 gg = ((const float2*)g)[tid];
    float2 bb = ((const float2*)b)[tid];
    out2[tid] = make_float2(d0*rstd*gg.x + bb.x, d1*rstd*gg.y + bb.y);
}

__global__ void landmarks_k(const float* __restrict__ qkv,
                            float* __restrict__ QL, float* __restrict__ KL)
{
    int idx = blockIdx.x * blockDim.x + threadIdx.x;
    if (idx >= HEADS*NL*DH) return;
    int h = idx / (NL*DH);
    int j = (idx / DH) % NL;
    int d = idx % DH;
    const float* qb = qkv + (long)(j*LCH)*QKVD + h*DH + d;
    const float* kb = qb + DIM;
    float sq = 0.f, sk = 0.f;
    for (int i = 0; i < LCH; i++) { sq += qb[(long)i*QKVD]; sk += kb[(long)i*QKVD]; }
    QL[idx] = sq * (1.f/LCH);
    KL[idx] = sk * (1.f/LCH);
}

__global__ void __launch_bounds__(128) softmax256(float* __restrict__ X) {
    long r = blockIdx.x;
    float2* x = (float2*)(X + r * (long)NL);
    int tid = threadIdx.x;
    float2 v = x[tid];
    __shared__ float sm[4];
    float m = fmaxf(v.x, v.y);
    #pragma unroll
    for (int o = 16; o; o >>= 1) m = fmaxf(m, __shfl_xor_sync(~0u, m, o));
    if ((tid & 31) == 0) sm[tid >> 5] = m;
    __syncthreads();
    m = fmaxf(fmaxf(sm[0], sm[1]), fmaxf(sm[2], sm[3]));
    __syncthreads();
    v.x = __expf(v.x - m); v.y = __expf(v.y - m);
    float s = v.x + v.y;
    #pragma unroll
    for (int o = 16; o; o >>= 1) s += __shfl_xor_sync(~0u, s, o);
    if ((tid & 31) == 0) sm[tid >> 5] = s;
    __syncthreads();
    float inv = 1.f / (sm[0]+sm[1]+sm[2]+sm[3]);
    x[tid] = make_float2(v.x * inv, v.y * inv);
}

__global__ void __launch_bounds__(256) softmax_wide(float* __restrict__ X) {
    long r = blockIdx.x;
    float* x = X + r * (long)NPAD;
    int tid = threadIdx.x;
    float4 v[15];
    #pragma unroll
    for (int i = 0; i < 15; i++) v[i] = *(float4*)&x[tid*4 + i*1024];
    __shared__ float sm[8];
    float m = -1e30f;
    #pragma unroll
    for (int i = 0; i < 15; i++)
        m = fmaxf(m, fmaxf(fmaxf(v[i].x, v[i].y), fmaxf(v[i].z, v[i].w)));
    #pragma unroll
    for (int o = 16; o; o >>= 1) m = fmaxf(m, __shfl_xor_sync(~0u, m, o));
    if ((tid & 31) == 0) sm[tid >> 5] = m;
    __syncthreads();
    m = fmaxf(fmaxf(fmaxf(sm[0],sm[1]),fmaxf(sm[2],sm[3])),
              fmaxf(fmaxf(sm[4],sm[5]),fmaxf(sm[6],sm[7])));
    __syncthreads();
    float s = 0.f;
    #pragma unroll
    for (int i = 0; i < 15; i++) {
        v[i].x = __expf(v[i].x - m); v[i].y = __expf(v[i].y - m);
        v[i].z = __expf(v[i].z - m); v[i].w = __expf(v[i].w - m);
        s += v[i].x + v[i].y + v[i].z + v[i].w;
    }
    #pragma unroll
    for (int o = 16; o; o >>= 1) s += __shfl_xor_sync(~0u, s, o);
    if ((tid & 31) == 0) sm[tid >> 5] = s;
    __syncthreads();
    float inv = 1.f / (sm[0]+sm[1]+sm[2]+sm[3]+sm[4]+sm[5]+sm[6]+sm[7]);
    #pragma unroll
    for (int i = 0; i < 15; i++) {
        v[i].x *= inv; v[i].y *= inv; v[i].z *= inv; v[i].w *= inv;
        *(float4*)&x[tid*4 + i*1024] = v[i];
    }
}

__global__ void __launch_bounds__(512) res_conv2(
    float* __restrict__ attn, const float* __restrict__ qkv,
    const float* __restrict__ w)
{
    int t0 = blockIdx.x * 8;
    int ch = threadIdx.x;
    int h = ch >> 6;
    float wk[33];
    #pragma unroll
    for (int k = 0; k < 33; k++) wk[k] = w[h*33 + k];
    float v[40];
    #pragma unroll
    for (int j = 0; j < 40; j++) {
        int tt = t0 + j - 16;
        v[j] = (tt >= 0 && tt < NPAD) ? qkv[(long)tt*QKVD + 2*DIM + ch] : 0.f;
    }
    #pragma unroll
    for (int j = 0; j < 8; j++) {
        float s = 0.f;
        #pragma unroll
        for (int k = 0; k < 33; k++) s += wk[k] * v[j + k];
        attn[(long)(t0 + j)*DIM + ch] = s;
    }
}

// PPEG v3: smem-tiled image halo (7 x 22 x 128ch), weights in registers.
#define PPW 16
#define PPEG_SMEM (154*128*4)
__global__ void __launch_bounds__(128) ppeg3(
    const float* __restrict__ h, float* __restrict__ out,
    const float* __restrict__ w7, const float* __restrict__ b7,
    const float* __restrict__ w5, const float* __restrict__ b5,
    const float* __restrict__ w3, const float* __restrict__ b3)
{
    extern __shared__ float tl[];   // [154][128]
    const int tid = threadIdx.x;
    const int ch = blockIdx.z * 128 + tid;
    float wcr[49];
    #pragma unroll
    for (int k = 0; k < 49; k++) {
        int dy = k / 7 - 3, dx = k % 7 - 3;
        float wv = w7[(long)ch*49 + k];
        if (dy >= -2 && dy <= 2 && dx >= -2 && dx <= 2)
            wv += w5[(long)ch*25 + (dy+2)*5 + (dx+2)];
        if (dy >= -1 && dy <= 1 && dx >= -1 && dx <= 1)
            wv += w3[(long)ch*9 + (dy+1)*3 + (dx+1)];
        if (k == 24) wv += 1.f;
        wcr[k] = wv;
    }
    const float bias_c = b7[ch] + b5[ch] + b3[ch];
    const int r = blockIdx.y;
    const int c0 = blockIdx.x * PPW;

    for (int s = 0; s < 154; s++) {
        int dy = s / 22, dx = s % 22;
        int rr = r - 3 + dy, cc = c0 - 3 + dx;
        float v = 0.f;
        if (rr >= 0 && rr < IMGH && cc >= 0 && cc < IMGH)
            v = h[(long)(1 + rr*IMGH + cc)*DIM + ch];
        tl[s*128 + tid] = v;
    }
    __syncthreads();

    #pragma unroll 1
    for (int pp = 0; pp < PPW; pp++) {
        int c = c0 + pp;
        if (c >= IMGH) break;
        float acc = bias_c;
        #pragma unroll
        for (int k = 0; k < 49; k++) {
            int dy = k / 7, dx = k % 7;
            acc += tl[(dy*22 + pp + dx)*128 + tid] * wcr[k];
        }
        out[(long)(r*IMGH + c)*DIM + ch] = acc;
    }
}

__global__ void ppeg_copyback(float* __restrict__ h, const float* __restrict__ y) {
    long i = (long)blockIdx.x * blockDim.x + threadIdx.x;
    if (i < (long)NPIX*DIM) h[DIM + i] = y[i];
}

__global__ void final_head(const float* __restrict__ h, const float* __restrict__ g,
                           const float* __restrict__ b, const float* __restrict__ W,
                           const float* __restrict__ bias, float* __restrict__ out,
                           int out_size)
{
    __shared__ float red[512];
    __shared__ float xn[512];
    int tid = threadIdx.x;
    float x = h[tid];
    red[tid] = x; __syncthreads();
    for (int st = 256; st > 0; st >>= 1) {
        if (tid < st) red[tid] += red[tid+st];
        __syncthreads();
    }
    float mu = red[0] / DIM; __syncthreads();
    float d = x - mu;
    red[tid] = d*d; __syncthreads();
    for (int st = 256; st > 0; st >>= 1) {
        if (tid < st) red[tid] += red[tid+st];
        __syncthreads();
    }
    float rstd = rsqrtf(red[0]/DIM + 1e-5f); __syncthreads();
    xn[tid] = d*rstd*g[tid] + b[tid];
    __syncthreads();
    if (tid < 5) {
        float s = bias[tid];
        for (int c = 0; c < DIM; c++) s += xn[c] * W[c*5 + tid];
        red[tid] = s;
    }
    __syncthreads();
    if (tid == 0) {
        float lg[5], mx = -1e30f;
        for (int j = 0; j < 5; j++) { lg[j] = red[j]; mx = fmaxf(mx, lg[j]); }
        float se = 0.f, pr[5];
        for (int j = 0; j < 5; j++) { pr[j] = expf(lg[j]-mx); se += pr[j]; }
        int am = 0;
        for (int j = 1; j < 5; j++) if (lg[j] > lg[am]) am = j;
        for (int j = 0; j < 5; j++) {
            if (j < out_size)     out[j]     = lg[j];
            if (5 + j < out_size) out[5 + j] = pr[j]/se;
        }
        if (10 < out_size) out[10] = (float)am;
        for (int j = 11; j < out_size; j++) out[j] = 0.f;
    }
}

// ---------------- host orchestration ----------------
struct Ptrs {
    float *h, *xln, *qkv, *QL, *KL, *A3;
    float *S2, *XZ, *T1, *T2, *Z, *Z2, *T, *U, *attn, *y, *scal;
};

static void get_ptrs(Ptrs& P) {
    cudaGetSymbolAddress((void**)&P.h,    g_h);
    cudaGetSymbolAddress((void**)&P.xln,  g_xln);
    cudaGetSymbolAddress((void**)&P.qkv,  g_qkv);
    cudaGetSymbolAddress((void**)&P.QL,   g_QL);
    cudaGetSymbolAddress((void**)&P.KL,   g_KL);
    cudaGetSymbolAddress((void**)&P.A3,   g_A3);
    cudaGetSymbolAddress((void**)&P.S2,   g_S2);
    cudaGetSymbolAddress((void**)&P.XZ,   g_XZ);
    cudaGetSymbolAddress((void**)&P.T1,   g_T1);
    cudaGetSymbolAddress((void**)&P.T2,   g_T2);
    cudaGetSymbolAddress((void**)&P.Z,    g_Zb);
    cudaGetSymbolAddress((void**)&P.Z2,   g_Z2b);
    cudaGetSymbolAddress((void**)&P.T,    g_Tb);
    cudaGetSymbolAddress((void**)&P.U,    g_Ub);
    cudaGetSymbolAddress((void**)&P.attn, g_attn);
    cudaGetSymbolAddress((void**)&P.y,    g_y);
    cudaGetSymbolAddress((void**)&P.scal, g_scal);
}

#define MMA_BIG_NN  gemm_mma<128,128,64,32,false,false>
#define MMA_BIG_NT  gemm_mma<128,128,64,32,true ,false>
#define MMA_SM_NN   gemm_mma<64,64,32,32,false,false>
#define MMA_SM_NT   gemm_mma<64,64,32,32,true ,false>
#define MMA_SM_SPK  gemm_mma<64,64,32,32,false,true >

static inline dim3 grid128(int M, int N, int batch) {
    return dim3(N / 128, (M + 127) / 128, batch);
}
static inline dim3 grid64(int M, int N, int batch) {
    return dim3(N / 64, (M + 63) / 64, batch);
}

static void run_attention(const Ptrs& P, const float* lng, const float* lnb,
                          const float* Wqkv, const float* Wout, const float* bout,
                          const float* resw)
{
    const long sLnd = (long)NL*DH;
    const long sQ   = (long)NL*NL;
    const float QS = 0.125f;

    const float* Kv = P.qkv + DIM;
    const float* Vv = P.qkv + 2*DIM;

    ln_pad<<<NPAD, 256>>>(P.h, P.xln, lng, lnb);
    MMA_BIG_NN<<<grid128(NPAD, 3*DIM, 1), 256>>>(
        P.xln, Wqkv, P.qkv, NPAD, 3*DIM, DIM, DIM, 3*DIM, 3*DIM,
        0, 0, 0, 1.f, 0.f, 0.f, nullptr, 0);
    res_conv2<<<NPAD/8, 512>>>(P.attn, P.qkv, resw);
    landmarks_k<<<(HEADS*NL*DH + 255)/256, 256>>>(P.qkv, P.QL, P.KL);
    MMA_SM_NT<<<grid64(NL, NL, HEADS), 128>>>(
        P.QL, P.KL, P.S2, NL, NL, DH, DH, DH, NL,
        sLnd, sLnd, sQ, QS, 0.f, 0.f, nullptr, 0);
    softmax256<<<HEADS*NL, 128>>>(P.S2);
    pinv_persist<<<PBLOCKS, 128>>>(P.S2, P.Z, P.Z2, P.XZ, P.T1, P.T2, P.scal);
    MMA_BIG_NT<<<grid128(NL, NPAD, HEADS), 256>>>(
        P.QL, Kv, P.A3, NL, NPAD, DH, DH, QKVD, NPAD,
        sLnd, (long)DH, (long)NL*NPAD, QS, 0.f, 0.f, nullptr, 0);
    softmax_wide<<<HEADS*NL, 256>>>(P.A3);
    zero_kernel<<<(HEADS*NL*DH + 255)/256, 256>>>(P.T, (long)HEADS*NL*DH);
    MMA_SM_SPK<<<grid64(NL, DH, HEADS*NSPLIT), 128>>>(
        P.A3, Vv, P.T, NL, DH, NPAD, NPAD, QKVD, DH,
        (long)NL*NPAD, (long)DH, sLnd, 1.f, 0.f, 0.f, nullptr, 0);
    MMA_SM_NN<<<grid64(NL, DH, HEADS), 128>>>(
        P.Z, P.T, P.U, NL, DH, NL, NL, DH, DH,
        sQ, sLnd, sLnd, 1.f, 0.f, 0.f, nullptr, 0);
    attn1_fused<<<dim3(NPAD/64, HEADS), 128, A1_SMEMB>>>(P.qkv, P.KL, P.U, P.attn);
    MMA_BIG_NN<<<grid128(NPAD, DIM, 1), 256>>>(
        P.attn, Wout, P.h, NPAD, DIM, DIM, DIM, DIM, DIM,
        0, 0, 0, 1.f, 0.f, 0.f, bout, 2);
}

extern "C" void kernel_launch(void* const* d_in, const int* in_sizes, int n_in,
                              void* d_out, int out_size)
{
    const float* data      = (const float*)d_in[0];
    const float* W_fc1     = (const float*)d_in[1];
    const float* b_fc1     = (const float*)d_in[2];
    const float* cls_token = (const float*)d_in[3];
    const float* ln1_g     = (const float*)d_in[4];
    const float* ln1_b     = (const float*)d_in[5];
    const float* qkv1      = (const float*)d_in[6];
    const float* out1_w    = (const float*)d_in[7];
    const float* out1_b    = (const float*)d_in[8];
    const float* res1      = (const float*)d_in[9];
    const float* w7        = (const float*)d_in[10];
    const float* b7        = (const float*)d_in[11];
    const float* w5        = (const float*)d_in[12];
    const float* b5        = (const float*)d_in[13];
    const float* w3        = (const float*)d_in[14];
    const float* b3        = (const float*)d_in[15];
    const float* ln2_g     = (const float*)d_in[16];
    const float* ln2_b     = (const float*)d_in[17];
    const float* qkv2      = (const float*)d_in[18];
    const float* out2_w    = (const float*)d_in[19];
    const float* out2_b    = (const float*)d_in[20];
    const float* res2      = (const float*)d_in[21];
    const float* norm_g    = (const float*)d_in[22];
    const float* norm_b    = (const float*)d_in[23];
    const float* W_fc2     = (const float*)d_in[24];
    const float* b_fc2     = (const float*)d_in[25];

    Ptrs P;
    get_ptrs(P);

    cudaFuncSetAttribute(attn1_fused,
        cudaFuncAttributeMaxDynamicSharedMemorySize, A1_SMEMB);
    cudaFuncSetAttribute(ppeg3,
        cudaFuncAttributeMaxDynamicSharedMemorySize, PPEG_SMEM);

    set_cls<<<1, DIM>>>(P.h, cls_token);
    MMA_BIG_NN<<<grid128(15000, DIM, 1), 256>>>(
        data, W_fc1, P.h + DIM, 15000, DIM, 1024, 1024, DIM, DIM,
        0, 0, 0, 1.f, 0.f, 0.f, b_fc1, 1);
    dup_rows<<<(129*DIM + 255)/256, 256>>>(P.h);

    run_attention(P, ln1_g, ln1_b, qkv1, out1_w, out1_b, res1);

    ppeg3<<<dim3((IMGH + PPW - 1)/PPW, IMGH, DIM/128), 128, PPEG_SMEM>>>(
        P.h, P.y, w7, b7, w5, b5, w3, b3);
    ppeg_copyback<<<(int)(((long)NPIX*DIM + 255)/256), 256>>>(P.h, P.y);

    run_attention(P, ln2_g, ln2_b, qkv2, out2_w, out2_b, res2);

    final_head<<<1, DIM>>>(P.h, norm_g, norm_b, W_fc2, b_fc2, (float*)d_out, out_size);
}

// round 14
// speedup vs baseline: 1.0411x; 1.0411x over previous
#include <cuda_runtime.h>
#include <math.h>
#include <stdint.h>

#define HEADS 8
#define DH    64
#define DIM   512
#define QKVD  1536
#define NTOK  15130
#define NPAD  15360
#define PADR  230
#define NL    256
#define LCH   60
#define IMGH  123
#define NPIX  15129
#define NSPLIT 16
#define PBLOCKS 128

// ---------------- static scratch (allocation-free rule) ----------------
__device__ __align__(16) float g_h   [NTOK*DIM];
__device__ __align__(16) float g_xln [NPAD*DIM];
__device__ __align__(16) float g_qkv [NPAD*3*DIM];
__device__ __align__(16) float g_QL  [HEADS*NL*DH];
__device__ __align__(16) float g_KL  [HEADS*NL*DH];
__device__ __align__(16) float g_A3  [HEADS*NL*NPAD];
__device__ __align__(16) float g_S2  [HEADS*NL*NL];
__device__ __align__(16) float g_XZ  [HEADS*NL*NL];
__device__ __align__(16) float g_T1  [HEADS*NL*NL];
__device__ __align__(16) float g_T2  [HEADS*NL*NL];
__device__ __align__(16) float g_Zb  [HEADS*NL*NL];
__device__ __align__(16) float g_Z2b [HEADS*NL*NL];
__device__ __align__(16) float g_Tb  [HEADS*NL*DH];
__device__ __align__(16) float g_Ub  [HEADS*NL*DH];
__device__ __align__(16) float g_attn[NPAD*DIM];
__device__ __align__(16) float g_y   [NPAD*DIM];
__device__ float g_scal[2];
__device__ unsigned g_bar_cnt = 0;
__device__ volatile unsigned g_bar_gen = 0;

// ================= bf16 split primitives =================
__device__ __forceinline__ uint32_t pkbf(float x0, float x1) {
    uint32_t r;
    asm("cvt.rn.bf16x2.f32 %0, %1, %2;" : "=r"(r) : "f"(x1), "f"(x0));
    return r;
}
__device__ __forceinline__ float unlo(uint32_t p) {
    return __uint_as_float(p << 16);
}
__device__ __forceinline__ float unhi(uint32_t p) {
    return __uint_as_float(p & 0xFFFF0000u);
}
__device__ __forceinline__ void bsplit4(float4 v,
    uint32_t& h0, uint32_t& h1, uint32_t& l0, uint32_t& l1)
{
    h0 = pkbf(v.x, v.y);
    h1 = pkbf(v.z, v.w);
    l0 = pkbf(v.x - unlo(h0), v.y - unhi(h0));
    l1 = pkbf(v.z - unlo(h1), v.w - unhi(h1));
}
__device__ __forceinline__ void bsplit2(float x0, float x1, uint32_t& h, uint32_t& l) {
    h = pkbf(x0, x1);
    l = pkbf(x0 - unlo(h), x1 - unhi(h));
}
__device__ __forceinline__ void mma16(float* d,
    uint32_t a0, uint32_t a1, uint32_t a2, uint32_t a3,
    uint32_t b0, uint32_t b1)
{
    asm volatile("mma.sync.aligned.m16n8k16.row.col.f32.bf16.bf16.f32 "
        "{%0,%1,%2,%3},{%4,%5,%6,%7},{%8,%9},{%0,%1,%2,%3};"
        : "+f"(d[0]), "+f"(d[1]), "+f"(d[2]), "+f"(d[3])
        : "r"(a0), "r"(a1), "r"(a2), "r"(a3), "r"(b0), "r"(b1));
}
__device__ __forceinline__ void mma16_split(float* acc,
    const uint32_t* Ah, const uint32_t* Al, const uint32_t* Bh, const uint32_t* Bl)
{
    mma16(acc, Ah[0],Ah[1],Ah[2],Ah[3], Bh[0],Bh[1]);
    mma16(acc, Ah[0],Ah[1],Ah[2],Ah[3], Bl[0],Bl[1]);
    mma16(acc, Al[0],Al[1],Al[2],Al[3], Bh[0],Bh[1]);
}

#define PADS 4

// ================= generic bf16-split GEMM (batched, NN/NT, split-K) ============
// (R9-verified layout: k-pair-major packed tiles, scalar fragment LDS)
template<int BM, int BN, int WM, int WN, bool NT, bool SPLITK>
__global__ void __launch_bounds__((BM/WM)*(BN/WN)*32)
gemm_mma(const float* __restrict__ A, const float* __restrict__ B,
         float* __restrict__ C,
         int M, int N, int K, int lda, int ldb, int ldc,
         long sA, long sB, long sC,
         float alpha, float beta_diag, float gammaA,
         const float* __restrict__ bias, int mode)
{
    constexpr int NWARP = (BM/WM)*(BN/WN);
    constexpr int T = NWARP * 32;
    constexpr int NWN = BN / WN;
    constexpr int MT = WM / 16, NTL = WN / 8;
    static_assert(T == 8 * (BN / 4), "B-NN loader mapping requires T == 2*BN");

    int z = blockIdx.z;
    int kbeg = 0, kend = K;
    if (SPLITK) {
        int batch = z / NSPLIT, split = z % NSPLIT;
        A += (long)batch * sA; B += (long)batch * sB; C += (long)batch * sC;
        int chunk = K / NSPLIT;
        kbeg = split * chunk; kend = kbeg + chunk;
    } else {
        A += (long)z * sA; B += (long)z * sB; C += (long)z * sC;
    }

    __shared__ __align__(16) uint32_t sAh[2][8][BM + PADS];
    __shared__ __align__(16) uint32_t sAl[2][8][BM + PADS];
    __shared__ __align__(16) uint32_t sBh[2][8][BN + PADS];
    __shared__ __align__(16) uint32_t sBl[2][8][BN + PADS];

    const int tid = threadIdx.x;
    const int wid = tid >> 5, lane = tid & 31;
    const int g = lane >> 2, t = lane & 3;
    const int row0 = blockIdx.y * BM;
    const int col0 = blockIdx.x * BN;
    const int wm0 = (wid / NWN) * WM;
    const int wn0 = (wid % NWN) * WN;

    float4 ra[2], rb[2];

    auto load_g = [&](int k0) {
        #pragma unroll
        for (int it = 0; it < 2; it++) {
            int i = tid + it * T;
            int m = i >> 2, kq = (i & 3) * 4;
            int gm = row0 + m;
            ra[it] = make_float4(0.f, 0.f, 0.f, 0.f);
            if (gm < M) ra[it] = *(const float4*)&A[(long)gm * lda + k0 + kq];
        }
        if (!NT) {
            int k2 = tid / (BN / 4), ng = (tid % (BN / 4)) * 4;
            rb[0] = *(const float4*)&B[(long)(k0 + 2*k2)     * ldb + col0 + ng];
            rb[1] = *(const float4*)&B[(long)(k0 + 2*k2 + 1) * ldb + col0 + ng];
        } else {
            #pragma unroll
            for (int it = 0; it < 2; it++) {
                int i = tid + it * T;
                int n = i >> 2, kq = (i & 3) * 4;
                rb[it] = make_float4(0.f, 0.f, 0.f, 0.f);
                if (col0 + n < N)
                    rb[it] = *(const float4*)&B[(long)(col0 + n) * ldb + k0 + kq];
            }
        }
    };
    auto store_s = [&](int buf) {
        #pragma unroll
        for (int it = 0; it < 2; it++) {
            int i = tid + it * T;
            int m = i >> 2, kp = (i & 3) * 2;
            uint32_t h0, h1, l0, l1;
            bsplit4(ra[it], h0, h1, l0, l1);
            sAh[buf][kp][m]     = h0;
            sAh[buf][kp + 1][m] = h1;
            sAl[buf][kp][m]     = l0;
            sAl[buf][kp + 1][m] = l1;
        }
        if (!NT) {
            int k2 = tid / (BN / 4), ng = (tid % (BN / 4)) * 4;
            const float* v0 = &rb[0].x;
            const float* v1 = &rb[1].x;
            uint32_t hh[4], ll[4];
            #pragma unroll
            for (int q = 0; q < 4; q++) {
                uint32_t h = pkbf(v0[q], v1[q]);
                hh[q] = h;
                ll[q] = pkbf(v0[q] - unlo(h), v1[q] - unhi(h));
            }
            *(uint4*)&sBh[buf][k2][ng] = *(uint4*)hh;
            *(uint4*)&sBl[buf][k2][ng] = *(uint4*)ll;
        } else {
            #pragma unroll
            for (int it = 0; it < 2; it++) {
                int i = tid + it * T;
                int n = i >> 2, kp = (i & 3) * 2;
                uint32_t h0, h1, l0, l1;
                bsplit4(rb[it], h0, h1, l0, l1);
                sBh[buf][kp][n]     = h0;
                sBh[buf][kp + 1][n] = h1;
                sBl[buf][kp][n]     = l0;
                sBl[buf][kp + 1][n] = l1;
            }
        }
    };

    float acc[MT][NTL][4];
    #pragma unroll
    for (int i = 0; i < MT; i++)
        #pragma unroll
        for (int j = 0; j < NTL; j++)
            #pragma unroll
            for (int q = 0; q < 4; q++) acc[i][j][q] = 0.f;

    const int ntiles = (kend - kbeg) / 16;
    load_g(kbeg);
    store_s(0);
    __syncthreads();

    for (int kt = 0; kt < ntiles; kt++) {
        if (kt + 1 < ntiles) load_g(kbeg + (kt + 1) * 16);
        int buf = kt & 1;
        {
            uint32_t Ahf[MT][4], Alf[MT][4], Bhf[NTL][2], Blf[NTL][2];
            #pragma unroll
            for (int mt = 0; mt < MT; mt++) {
                int mb = wm0 + mt * 16 + g;
                Ahf[mt][0] = sAh[buf][t    ][mb];
                Ahf[mt][1] = sAh[buf][t    ][mb + 8];
                Ahf[mt][2] = sAh[buf][t + 4][mb];
                Ahf[mt][3] = sAh[buf][t + 4][mb + 8];
                Alf[mt][0] = sAl[buf][t    ][mb];
                Alf[mt][1] = sAl[buf][t    ][mb + 8];
                Alf[mt][2] = sAl[buf][t + 4][mb];
                Alf[mt][3] = sAl[buf][t + 4][mb + 8];
            }
            #pragma unroll
            for (int nt = 0; nt < NTL; nt++) {
                int nb = wn0 + nt * 8 + g;
                Bhf[nt][0] = sBh[buf][t    ][nb];
                Bhf[nt][1] = sBh[buf][t + 4][nb];
                Blf[nt][0] = sBl[buf][t    ][nb];
                Blf[nt][1] = sBl[buf][t + 4][nb];
            }
            #pragma unroll
            for (int mt = 0; mt < MT; mt++)
                #pragma unroll
                for (int nt = 0; nt < NTL; nt++)
                    mma16_split(acc[mt][nt], Ahf[mt], Alf[mt], Bhf[nt], Blf[nt]);
        }
        if (kt + 1 < ntiles) {
            store_s((kt + 1) & 1);
            __syncthreads();
        }
    }

    auto emit = [&](int r, int c, float v0, float v1) {
        if (r >= M) return;
        v0 *= alpha; v1 *= alpha;
        if (bias) { v0 += bias[c]; v1 += bias[c + 1]; }
        if (beta_diag != 0.f) {
            if (r == c)     v0 += beta_diag;
            if (r == c + 1) v1 += beta_diag;
        }
        if (gammaA != 0.f) {
            v0 += gammaA * A[(long)r * lda + c];
            v1 += gammaA * A[(long)r * lda + c + 1];
        }
        if (mode == 1) { v0 = fmaxf(v0, 0.f); v1 = fmaxf(v1, 0.f); }
        if (SPLITK) {
            atomicAdd(&C[(long)r * ldc + c], v0);
            atomicAdd(&C[(long)r * ldc + c + 1], v1);
        } else if (mode == 2) {
            if (r >= PADR) {
                float2* dst = (float2*)&C[(long)(r - PADR) * ldc + c];
                float2 o = *dst;
                o.x += v0; o.y += v1;
                *dst = o;
            }
        } else {
            *(float2*)&C[(long)r * ldc + c] = make_float2(v0, v1);
        }
    };
    #pragma unroll
    for (int mt = 0; mt < MT; mt++)
        #pragma unroll
        for (int nt = 0; nt < NTL; nt++) {
            int r = row0 + wm0 + mt * 16 + g;
            int c = col0 + wn0 + nt * 8 + 2 * t;
            emit(r,     c, acc[mt][nt][0], acc[mt][nt][1]);
            emit(r + 8, c, acc[mt][nt][2], acc[mt][nt][3]);
        }
}

// ================= persistent pinv kernel (bf16 split) =================
__device__ __forceinline__ void atomicMaxFloatPos(float* addr, float v) {
    atomicMax((int*)addr, __float_as_int(v));
}

__device__ __forceinline__ void gridbar() {
    __syncthreads();
    if (threadIdx.x == 0) {
        unsigned gen = g_bar_gen;
        __threadfence();
        if (atomicAdd(&g_bar_cnt, 1u) == PBLOCKS - 1) {
            g_bar_cnt = 0;
            __threadfence();
            g_bar_gen = gen + 1;
        } else {
            while (g_bar_gen == gen) { __nanosleep(64); }
        }
        __threadfence();
    }
    __syncthreads();
}

typedef uint32_t pktile[2][8][68];

__device__ __noinline__ void gemm64_dev(
    const float* __restrict__ A, const float* __restrict__ B, float* __restrict__ C,
    int row0, int col0, float alpha, float beta_diag, float gammaA,
    pktile& Ah, pktile& Al, pktile& Bh, pktile& Bl)
{
    const int tid = threadIdx.x;
    const int wid = tid >> 5, lane = tid & 31;
    const int g = lane >> 2, t = lane & 3;
    const int wm0 = (wid >> 1) * 32, wn0 = (wid & 1) * 32;

    float4 ra[2], rb0, rb1;
    const int k2 = tid >> 4, ng = (tid & 15) * 4;

    auto load_g = [&](int k0) {
        #pragma unroll
        for (int it = 0; it < 2; it++) {
            int i = tid + it * 128;
            int m = i >> 2, kq = (i & 3) * 4;
            ra[it] = *(const float4*)&A[(long)(row0 + m) * 256 + k0 + kq];
        }
        rb0 = *(const float4*)&B[(long)(k0 + 2*k2)     * 256 + col0 + ng];
        rb1 = *(const float4*)&B[(long)(k0 + 2*k2 + 1) * 256 + col0 + ng];
    };
    auto store_s = [&](int buf) {
        #pragma unroll
        for (int it = 0; it < 2; it++) {
            int i = tid + it * 128;
            int m = i >> 2, kp = (i & 3) * 2;
            uint32_t h0, h1, l0, l1;
            bsplit4(ra[it], h0, h1, l0, l1);
            Ah[buf][kp][m]     = h0;
            Ah[buf][kp + 1][m] = h1;
            Al[buf][kp][m]     = l0;
            Al[buf][kp + 1][m] = l1;
        }
        const float* v0 = &rb0.x;
        const float* v1 = &rb1.x;
        uint32_t hh[4], ll[4];
        #pragma unroll
        for (int q = 0; q < 4; q++) {
            uint32_t h = pkbf(v0[q], v1[q]);
            hh[q] = h;
            ll[q] = pkbf(v0[q] - unlo(h), v1[q] - unhi(h));
        }
        *(uint4*)&Bh[buf][k2][ng] = *(uint4*)hh;
        *(uint4*)&Bl[buf][k2][ng] = *(uint4*)ll;
    };

    float acc[2][4][4] = {};
    load_g(0);
    store_s(0);
    __syncthreads();
    for (int kt = 0; kt < 16; kt++) {
        if (kt + 1 < 16) load_g((kt + 1) * 16);
        int buf = kt & 1;
        {
            uint32_t Ahf[2][4], Alf[2][4], Bhf[4][2], Blf[4][2];
            #pragma unroll
            for (int mt = 0; mt < 2; mt++) {
                int mb = wm0 + mt * 16 + g;
                Ahf[mt][0] = Ah[buf][t    ][mb];
                Ahf[mt][1] = Ah[buf][t    ][mb + 8];
                Ahf[mt][2] = Ah[buf][t + 4][mb];
                Ahf[mt][3] = Ah[buf][t + 4][mb + 8];
                Alf[mt][0] = Al[buf][t    ][mb];
                Alf[mt][1] = Al[buf][t    ][mb + 8];
                Alf[mt][2] = Al[buf][t + 4][mb];
                Alf[mt][3] = Al[buf][t + 4][mb + 8];
            }
            #pragma unroll
            for (int nt = 0; nt < 4; nt++) {
                int nb = wn0 + nt * 8 + g;
                Bhf[nt][0] = Bh[buf][t    ][nb];
                Bhf[nt][1] = Bh[buf][t + 4][nb];
                Blf[nt][0] = Bl[buf][t    ][nb];
                Blf[nt][1] = Bl[buf][t + 4][nb];
            }
            #pragma unroll
            for (int mt = 0; mt < 2; mt++)
                #pragma unroll
                for (int nt = 0; nt < 4; nt++)
                    mma16_split(acc[mt][nt], Ahf[mt], Alf[mt], Bhf[nt], Blf[nt]);
        }
        if (kt + 1 < 16) {
            store_s((kt + 1) & 1);
            __syncthreads();
        }
    }
    #pragma unroll
    for (int mt = 0; mt < 2; mt++)
        #pragma unroll
        for (int nt = 0; nt < 4; nt++) {
            int r0 = row0 + wm0 + mt * 16 + g;
            int c = col0 + wn0 + nt * 8 + 2 * t;
            #pragma unroll
            for (int half = 0; half < 2; half++) {
                int r = r0 + half * 8;
                float v0 = alpha * acc[mt][nt][half*2 + 0];
                float v1 = alpha * acc[mt][nt][half*2 + 1];
                if (beta_diag != 0.f) {
                    if (r == c)     v0 += beta_diag;
                    if (r == c + 1) v1 += beta_diag;
                }
                if (gammaA != 0.f) {
                    v0 += gammaA * A[(long)r * 256 + c];
                    v1 += gammaA * A[(long)r * 256 + c + 1];
                }
                *(float2*)&C[(long)r * 256 + c] = make_float2(v0, v1);
            }
        }
    __syncthreads();
}

__global__ void __launch_bounds__(128) pinv_persist(
    const float* __restrict__ S2, float* __restrict__ Z, float* __restrict__ Z2,
    float* __restrict__ XZ, float* __restrict__ T1, float* __restrict__ T2,
    float* __restrict__ scal)
{
    __shared__ __align__(16) uint32_t Ah[2][8][68], Al[2][8][68];
    __shared__ __align__(16) uint32_t Bh[2][8][68], Bl[2][8][68];
    const int b = blockIdx.x, tid = threadIdx.x;
    const int wid = tid >> 5, lane = tid & 31;

    if (b == 0 && tid < 2) scal[tid] = 0.f;
    gridbar();

    for (int q = 0; q < 8; q++) {
        int idx = b * 32 + wid * 8 + q;
        int mode = idx >> 11, rem = idx & 2047;
        int h = rem >> 8, i = rem & 255;
        const float* base = S2 + (long)h * 65536;
        float s = 0.f;
        if (mode == 0) { for (int j = lane; j < 256; j += 32) s += fabsf(base[i * 256 + j]); }
        else           { for (int j = lane; j < 256; j += 32) s += fabsf(base[j * 256 + i]); }
        #pragma unroll
        for (int o = 16; o; o >>= 1) s += __shfl_xor_sync(~0u, s, o);
        if (lane == 0) atomicMaxFloatPos(&scal[mode], s);
    }
    gridbar();

    float denom = scal[0] * scal[1];
    for (int l = 0; l < 32; l++) {
        int idx = b * 4096 + l * 128 + tid;
        int h = idx >> 16, rc = idx & 65535, r = rc >> 8, c = rc & 255;
        Z[idx] = S2[(long)h * 65536 + (long)c * 256 + r] / denom;
    }
    gridbar();

    const int head = b >> 4, tt = b & 15;
    const int row0 = (tt >> 2) * 64, col0 = (tt & 3) * 64;
    const long ho = (long)head * 65536;

    for (int it = 0; it < 6; it++) {
        float* zin  = (it & 1) ? Z2 : Z;
        float* zout = (it & 1) ? Z  : Z2;
        gemm64_dev(S2 + ho, zin + ho, XZ + ho, row0, col0, 1.f, 0.f, 0.f, Ah, Al, Bh, Bl);
        gridbar();
        gemm64_dev(XZ + ho, XZ + ho, T2 + ho, row0, col0, 1.f, 15.f, -7.f, Ah, Al, Bh, Bl);
        gridbar();
        gemm64_dev(XZ + ho, T2 + ho, T1 + ho, row0, col0, -1.f, 13.f, 0.f, Ah, Al, Bh, Bl);
        gridbar();
        gemm64_dev(zin + ho, T1 + ho, zout + ho, row0, col0, 0.25f, 0.f, 0.f, Ah, Al, Bh, Bl);
        gridbar();
    }
}

// ================= fused a1 attention (bf16 split): attn += softmax(P)@U ========
#define A1_AQH   0
#define A1_AQL   (32*68)
#define A1_BKH   (2*32*68)
#define A1_BKL   (2*32*68 + 32*260)
#define A1_PH    0
#define A1_PL    (128*68)
#define A1_ST    20992
#define A1_UH    37632
#define A1_UL    (37632 + 128*68)
#define A1_RINV  55040
#define A1_SMEMB (55104*4)

__global__ void __launch_bounds__(128) attn1_fused(
    const float* __restrict__ qkv, const float* __restrict__ KL,
    const float* __restrict__ U, float* __restrict__ attn)
{
    extern __shared__ float sm[];
    uint32_t* AQh = (uint32_t*)sm + A1_AQH;
    uint32_t* AQl = (uint32_t*)sm + A1_AQL;
    uint32_t* BKh = (uint32_t*)sm + A1_BKH;
    uint32_t* BKl = (uint32_t*)sm + A1_BKL;
    uint32_t* Ph  = (uint32_t*)sm + A1_PH;
    uint32_t* Pl  = (uint32_t*)sm + A1_PL;
    float*    ST  = sm + A1_ST;
    uint32_t* Uh  = (uint32_t*)sm + A1_UH;
    uint32_t* Ul  = (uint32_t*)sm + A1_UL;
    float*    rinv= sm + A1_RINV;

    const int tid = threadIdx.x;
    const int wid = tid >> 5, lane = tid & 31;
    const int g = lane >> 2, t = lane & 3;
    const int h = blockIdx.y;
    const int row0 = blockIdx.x * 64;
    const float* Qg  = qkv + h * DH;
    const float* KLh = KL + (long)h * NL * DH;
    const float* Ug  = U  + (long)h * NL * DH;

    #pragma unroll
    for (int l = 0; l < 8; l++) {
        int i = tid + l * 128;
        int m = i >> 4, kq = (i & 15) * 4;
        float4 v = *(const float4*)&Qg[(long)(row0 + m) * QKVD + kq];
        uint32_t h0, h1, l0, l1;
        bsplit4(v, h0, h1, l0, l1);
        int kp = kq >> 1;
        AQh[kp*68 + m] = h0; AQh[(kp+1)*68 + m] = h1;
        AQl[kp*68 + m] = l0; AQl[(kp+1)*68 + m] = l1;
    }
    #pragma unroll
    for (int l = 0; l < 32; l++) {
        int i = tid + l * 128;
        int n = i >> 4, kq = (i & 15) * 4;
        float4 v = *(const float4*)&KLh[n * 64 + kq];
        uint32_t h0, h1, l0, l1;
        bsplit4(v, h0, h1, l0, l1);
        int kp = kq >> 1;
        BKh[kp*260 + n] = h0; BKh[(kp+1)*260 + n] = h1;
        BKl[kp*260 + n] = l0; BKl[(kp+1)*260 + n] = l1;
    }
    #pragma unroll
    for (int l = 0; l < 16; l++) {
        int i = tid + l * 128;
        int kp = i >> 4, n4 = (i & 15) * 4;
        float4 v0 = *(const float4*)&Ug[(long)(2*kp)     * 64 + n4];
        float4 v1 = *(const float4*)&Ug[(long)(2*kp + 1) * 64 + n4];
        const float* p0 = &v0.x;
        const float* p1 = &v1.x;
        uint32_t hh[4], ll[4];
        #pragma unroll
        for (int q = 0; q < 4; q++) {
            uint32_t hq = pkbf(p0[q], p1[q]);
            hh[q] = hq;
            ll[q] = pkbf(p0[q] - unlo(hq), p1[q] - unhi(hq));
        }
        *(uint4*)&Uh[kp*68 + n4] = *(uint4*)hh;
        *(uint4*)&Ul[kp*68 + n4] = *(uint4*)ll;
    }
    __syncthreads();

    const int wm0 = (wid >> 1) * 32;
    const int wn1 = (wid & 1) * 128;
    {
        float acc1[2][16][4] = {};
        #pragma unroll
        for (int k16 = 0; k16 < 4; k16++) {
            int kb = k16 * 8;
            uint32_t Ahf[2][4], Alf[2][4];
            #pragma unroll
            for (int mt = 0; mt < 2; mt++) {
                int mb = wm0 + mt * 16 + g;
                Ahf[mt][0] = AQh[(kb + t    )*68 + mb];
                Ahf[mt][1] = AQh[(kb + t    )*68 + mb + 8];
                Ahf[mt][2] = AQh[(kb + t + 4)*68 + mb];
                Ahf[mt][3] = AQh[(kb + t + 4)*68 + mb + 8];
                Alf[mt][0] = AQl[(kb + t    )*68 + mb];
                Alf[mt][1] = AQl[(kb + t    )*68 + mb + 8];
                Alf[mt][2] = AQl[(kb + t + 4)*68 + mb];
                Alf[mt][3] = AQl[(kb + t + 4)*68 + mb + 8];
            }
            #pragma unroll
            for (int nt = 0; nt < 16; nt++) {
                int nb = wn1 + nt * 8 + g;
                uint32_t Bhf[2], Blf[2];
                Bhf[0] = BKh[(kb + t    )*260 + nb];
                Bhf[1] = BKh[(kb + t + 4)*260 + nb];
                Blf[0] = BKl[(kb + t    )*260 + nb];
                Blf[1] = BKl[(kb + t + 4)*260 + nb];
                mma16_split(acc1[0][nt], Ahf[0], Alf[0], Bhf, Blf);
                mma16_split(acc1[1][nt], Ahf[1], Alf[1], Bhf, Blf);
            }
        }
        #pragma unroll
        for (int mt = 0; mt < 2; mt++)
            #pragma unroll
            for (int nt = 0; nt < 16; nt++) {
                int r = wm0 + mt * 16 + g;
                int c = wn1 + nt * 8 + 2 * t;
                ST[c*65 + r]       = 0.125f * acc1[mt][nt][0];
                ST[(c+1)*65 + r]   = 0.125f * acc1[mt][nt][1];
                ST[c*65 + r+8]     = 0.125f * acc1[mt][nt][2];
                ST[(c+1)*65 + r+8] = 0.125f * acc1[mt][nt][3];
            }
    }
    __syncthreads();

    {
        int r = tid >> 1, half = tid & 1;
        int j0 = half * 128;
        float m = -1e30f;
        #pragma unroll 8
        for (int j = j0; j < j0 + 128; j++) m = fmaxf(m, ST[j*65 + r]);
        m = fmaxf(m, __shfl_xor_sync(~0u, m, 1));
        float s = 0.f;
        #pragma unroll 8
        for (int j = j0; j < j0 + 128; j++) {
            float e = __expf(ST[j*65 + r] - m);
            ST[j*65 + r] = e;
            s += e;
        }
        s += __shfl_xor_sync(~0u, s, 1);
        if (half == 0) rinv[r] = 1.f / s;
    }
    __syncthreads();

    #pragma unroll
    for (int l = 0; l < 64; l++) {
        int i = tid + l * 128;
        int kp = i >> 6, m = i & 63;
        float x0 = ST[(2*kp)     * 65 + m];
        float x1 = ST[(2*kp + 1) * 65 + m];
        uint32_t hq, lq;
        bsplit2(x0, x1, hq, lq);
        Ph[kp*68 + m] = hq;
        Pl[kp*68 + m] = lq;
    }
    __syncthreads();

    {
        const int wn2 = (wid & 1) * 32;
        float acc2[2][4][4] = {};
        #pragma unroll 4
        for (int k16 = 0; k16 < 16; k16++) {
            int kb = k16 * 8;
            uint32_t Ahf[2][4], Alf[2][4], Bhf[4][2], Blf[4][2];
            #pragma unroll
            for (int mt = 0; mt < 2; mt++) {
                int mb = wm0 + mt * 16 + g;
                Ahf[mt][0] = Ph[(kb + t    )*68 + mb];
                Ahf[mt][1] = Ph[(kb + t    )*68 + mb + 8];
                Ahf[mt][2] = Ph[(kb + t + 4)*68 + mb];
                Ahf[mt][3] = Ph[(kb + t + 4)*68 + mb + 8];
                Alf[mt][0] = Pl[(kb + t    )*68 + mb];
                Alf[mt][1] = Pl[(kb + t    )*68 + mb + 8];
                Alf[mt][2] = Pl[(kb + t + 4)*68 + mb];
                Alf[mt][3] = Pl[(kb + t + 4)*68 + mb + 8];
            }
            #pragma unroll
            for (int nt = 0; nt < 4; nt++) {
                int nb = wn2 + nt * 8 + g;
                Bhf[nt][0] = Uh[(kb + t    )*68 + nb];
                Bhf[nt][1] = Uh[(kb + t + 4)*68 + nb];
                Blf[nt][0] = Ul[(kb + t    )*68 + nb];
                Blf[nt][1] = Ul[(kb + t + 4)*68 + nb];
            }
            #pragma unroll
            for (int mt = 0; mt < 2; mt++)
                #pragma unroll
                for (int nt = 0; nt < 4; nt++)
                    mma16_split(acc2[mt][nt], Ahf[mt], Alf[mt], Bhf[nt], Blf[nt]);
        }
        #pragma unroll
        for (int mt = 0; mt < 2; mt++)
            #pragma unroll
            for (int nt = 0; nt < 4; nt++) {
                int rl = wm0 + mt * 16 + g;
                int c = h * DH + wn2 + nt * 8 + 2 * t;
                float i0 = rinv[rl], i1 = rinv[rl + 8];
                float2* d0 = (float2*)&attn[(long)(row0 + rl) * DIM + c];
                float2 o0 = *d0;
                o0.x += acc2[mt][nt][0] * i0;
                o0.y += acc2[mt][nt][1] * i0;
                *d0 = o0;
                float2* d1 = (float2*)&attn[(long)(row0 + rl + 8) * DIM + c];
                float2 o1 = *d1;
                o1.x += acc2[mt][nt][2] * i1;
                o1.y += acc2[mt][nt][3] * i1;
                *d1 = o1;
            }
    }
}

// ---------------- misc kernels ----------------
__global__ void zero_kernel(float* p, long n) {
    long i = (long)blockIdx.x * blockDim.x + threadIdx.x;
    if (i < n) p[i] = 0.f;
}

__global__ void set_cls(float* h, const float* __restrict__ cls) {
    h[threadIdx.x] = cls[threadIdx.x];
}

__global__ void dup_rows(float* h) {
    int i = blockIdx.x * blockDim.x + threadIdx.x;
    if (i < 129*DIM) {
        int t = i / DIM, c = i % DIM;
        h[(long)(15001 + t)*DIM + c] = h[(long)(1 + t)*DIM + c];
    }
}

__global__ void __launch_bounds__(256) ln_pad(
    const float* __restrict__ h, float* __restrict__ xo,
    const float* __restrict__ g, const float* __restrict__ b)
{
    int row = blockIdx.x, tid = threadIdx.x;
    float2* out2 = (float2*)(xo + (long)row * DIM);
    if (row < PADR) { out2[tid] = make_float2(0.f, 0.f); return; }
    const float2 xv = ((const float2*)(h + (long)(row - PADR) * DIM))[tid];
    __shared__ float sm1[8], sm2[8];
    float s = xv.x + xv.y;
    #pragma unroll
    for (int o = 16; o; o >>= 1) s += __shfl_xor_sync(~0u, s, o);
    if ((tid & 31) == 0) sm1[tid >> 5] = s;
    __syncthreads();
    float mu = (sm1[0]+sm1[1]+sm1[2]+sm1[3]+sm1[4]+sm1[5]+sm1[6]+sm1[7]) * (1.f/DIM);
    float d0 = xv.x - mu, d1 = xv.y - mu;
    float v = d0*d0 + d1*d1;
    #pragma unroll
    for (int o = 16; o; o >>= 1) v += __shfl_xor_sync(~0u, v, o);
    if ((tid & 31) == 0) sm2[tid >> 5] = v;
    __syncthreads();
    float var = (sm2[0]+sm2[1]+sm2[2]+sm2[3]+sm2[4]+sm2[5]+sm2[6]+sm2[7]) * (1.f/DIM);
    float rstd = rsqrtf(var + 1e-5f);
    float2 gg = ((const float2*)g)[tid];
    float2 bb = ((const float2*)b)[tid];
    out2[tid] = make_float2(d0*rstd*gg.x + bb.x, d1*rstd*gg.y + bb.y);
}

__global__ void landmarks_k(const float* __restrict__ qkv,
                            float* __restrict__ QL, float* __restrict__ KL)
{
    int idx = blockIdx.x * blockDim.x + threadIdx.x;
    if (idx >= HEADS*NL*DH) return;
    int h = idx / (NL*DH);
    int j = (idx / DH) % NL;
    int d = idx % DH;
    const float* qb = qkv + (long)(j*LCH)*QKVD + h*DH + d;
    const float* kb = qb + DIM;
    float sq = 0.f, sk = 0.f;
    for (int i = 0; i < LCH; i++) { sq += qb[(long)i*QKVD]; sk += kb[(long)i*QKVD]; }
    QL[idx] = sq * (1.f/LCH);
    KL[idx] = sk * (1.f/LCH);
}

__global__ void __launch_bounds__(128) softmax256(float* __restrict__ X) {
    long r = blockIdx.x;
    float2* x = (float2*)(X + r * (long)NL);
    int tid = threadIdx.x;
    float2 v = x[tid];
    __shared__ float sm[4];
    float m = fmaxf(v.x, v.y);
    #pragma unroll
    for (int o = 16; o; o >>= 1) m = fmaxf(m, __shfl_xor_sync(~0u, m, o));
    if ((tid & 31) == 0) sm[tid >> 5] = m;
    __syncthreads();
    m = fmaxf(fmaxf(sm[0], sm[1]), fmaxf(sm[2], sm[3]));
    __syncthreads();
    v.x = __expf(v.x - m); v.y = __expf(v.y - m);
    float s = v.x + v.y;
    #pragma unroll
    for (int o = 16; o; o >>= 1) s += __shfl_xor_sync(~0u, s, o);
    if ((tid & 31) == 0) sm[tid >> 5] = s;
    __syncthreads();
    float inv = 1.f / (sm[0]+sm[1]+sm[2]+sm[3]);
    x[tid] = make_float2(v.x * inv, v.y * inv);
}

__global__ void __launch_bounds__(256) softmax_wide(float* __restrict__ X) {
    long r = blockIdx.x;
    float* x = X + r * (long)NPAD;
    int tid = threadIdx.x;
    float4 v[15];
    #pragma unroll
    for (int i = 0; i < 15; i++) v[i] = *(float4*)&x[tid*4 + i*1024];
    __shared__ float sm[8];
    float m = -1e30f;
    #pragma unroll
    for (int i = 0; i < 15; i++)
        m = fmaxf(m, fmaxf(fmaxf(v[i].x, v[i].y), fmaxf(v[i].z, v[i].w)));
    #pragma unroll
    for (int o = 16; o; o >>= 1) m = fmaxf(m, __shfl_xor_sync(~0u, m, o));
    if ((tid & 31) == 0) sm[tid >> 5] = m;
    __syncthreads();
    m = fmaxf(fmaxf(fmaxf(sm[0],sm[1]),fmaxf(sm[2],sm[3])),
              fmaxf(fmaxf(sm[4],sm[5]),fmaxf(sm[6],sm[7])));
    __syncthreads();
    float s = 0.f;
    #pragma unroll
    for (int i = 0; i < 15; i++) {
        v[i].x = __expf(v[i].x - m); v[i].y = __expf(v[i].y - m);
        v[i].z = __expf(v[i].z - m); v[i].w = __expf(v[i].w - m);
        s += v[i].x + v[i].y + v[i].z + v[i].w;
    }
    #pragma unroll
    for (int o = 16; o; o >>= 1) s += __shfl_xor_sync(~0u, s, o);
    if ((tid & 31) == 0) sm[tid >> 5] = s;
    __syncthreads();
    float inv = 1.f / (sm[0]+sm[1]+sm[2]+sm[3]+sm[4]+sm[5]+sm[6]+sm[7]);
    #pragma unroll
    for (int i = 0; i < 15; i++) {
        v[i].x *= inv; v[i].y *= inv; v[i].z *= inv; v[i].w *= inv;
        *(float4*)&x[tid*4 + i*1024] = v[i];
    }
}

__global__ void __launch_bounds__(512) res_conv2(
    float* __restrict__ attn, const float* __restrict__ qkv,
    const float* __restrict__ w)
{
    int t0 = blockIdx.x * 8;
    int ch = threadIdx.x;
    int h = ch >> 6;
    float wk[33];
    #pragma unroll
    for (int k = 0; k < 33; k++) wk[k] = w[h*33 + k];
    float v[40];
    #pragma unroll
    for (int j = 0; j < 40; j++) {
        int tt = t0 + j - 16;
        v[j] = (tt >= 0 && tt < NPAD) ? qkv[(long)tt*QKVD + 2*DIM + ch] : 0.f;
    }
    #pragma unroll
    for (int j = 0; j < 8; j++) {
        float s = 0.f;
        #pragma unroll
        for (int k = 0; k < 33; k++) s += wk[k] * v[j + k];
        attn[(long)(t0 + j)*DIM + ch] = s;
    }
}

// PPEG v2 (R9-verified): combined 49-tap weights in smem; 128-ch slab, 16 px/block
#define PPP 16
__global__ void __launch_bounds__(128) ppeg2(
    const float* __restrict__ h, float* __restrict__ out,
    const float* __restrict__ w7, const float* __restrict__ b7,
    const float* __restrict__ w5, const float* __restrict__ b5,
    const float* __restrict__ w3, const float* __restrict__ b3)
{
    __shared__ float wc[49][128];
    int tid = threadIdx.x;
    int ch = blockIdx.y * 128 + tid;
    #pragma unroll
    for (int k = 0; k < 49; k++) {
        int dy = k / 7 - 3, dx = k % 7 - 3;
        float wv = w7[(long)ch*49 + k];
        if (dy >= -2 && dy <= 2 && dx >= -2 && dx <= 2)
            wv += w5[(long)ch*25 + (dy+2)*5 + (dx+2)];
        if (dy >= -1 && dy <= 1 && dx >= -1 && dx <= 1)
            wv += w3[(long)ch*9 + (dy+1)*3 + (dx+1)];
        if (k == 24) wv += 1.f;
        wc[k][tid] = wv;
    }
    float bias_c = b7[ch] + b5[ch] + b3[ch];
    __syncthreads();

    int p0 = blockIdx.x * PPP;
    #pragma unroll 1
    for (int pp = 0; pp < PPP; pp++) {
        int p = p0 + pp;
        if (p >= NPIX) break;
        int r = p / IMGH, c = p % IMGH;
        float acc = bias_c;
        if (r >= 3 && r < IMGH-3 && c >= 3 && c < IMGH-3) {
            #pragma unroll
            for (int k = 0; k < 49; k++) {
                int dy = k / 7 - 3, dx = k % 7 - 3;
                acc += h[(long)(1 + (r+dy)*IMGH + (c+dx))*DIM + ch] * wc[k][tid];
            }
        } else {
            #pragma unroll
            for (int k = 0; k < 49; k++) {
                int dy = k / 7 - 3, dx = k % 7 - 3;
                int rr = r + dy, cc = c + dx;
                if (rr >= 0 && rr < IMGH && cc >= 0 && cc < IMGH)
                    acc += h[(long)(1 + rr*IMGH + cc)*DIM + ch] * wc[k][tid];
            }
        }
        out[(long)p*DIM + ch] = acc;
    }
}

__global__ void ppeg_copyback(float* __restrict__ h, const float* __restrict__ y) {
    long i = (long)blockIdx.x * blockDim.x + threadIdx.x;
    if (i < (long)NPIX*DIM) h[DIM + i] = y[i];
}

__global__ void final_head(const float* __restrict__ h, const float* __restrict__ g,
                           const float* __restrict__ b, const float* __restrict__ W,
                           const float* __restrict__ bias, float* __restrict__ out,
                           int out_size)
{
    __shared__ float red[512];
    __shared__ float xn[512];
    int tid = threadIdx.x;
    float x = h[tid];
    red[tid] = x; __syncthreads();
    for (int st = 256; st > 0; st >>= 1) {
        if (tid < st) red[tid] += red[tid+st];
        __syncthreads();
    }
    float mu = red[0] / DIM; __syncthreads();
    float d = x - mu;
    red[tid] = d*d; __syncthreads();
    for (int st = 256; st > 0; st >>= 1) {
        if (tid < st) red[tid] += red[tid+st];
        __syncthreads();
    }
    float rstd = rsqrtf(red[0]/DIM + 1e-5f); __syncthreads();
    xn[tid] = d*rstd*g[tid] + b[tid];
    __syncthreads();
    if (tid < 5) {
        float s = bias[tid];
        for (int c = 0; c < DIM; c++) s += xn[c] * W[c*5 + tid];
        red[tid] = s;
    }
    __syncthreads();
    if (tid == 0) {
        float lg[5], mx = -1e30f;
        for (int j = 0; j < 5; j++) { lg[j] = red[j]; mx = fmaxf(mx, lg[j]); }
        float se = 0.f, pr[5];
        for (int j = 0; j < 5; j++) { pr[j] = expf(lg[j]-mx); se += pr[j]; }
        int am = 0;
        for (int j = 1; j < 5; j++) if (lg[j] > lg[am]) am = j;
        for (int j = 0; j < 5; j++) {
            if (j < out_size)     out[j]     = lg[j];
            if (5 + j < out_size) out[5 + j] = pr[j]/se;
        }
        if (10 < out_size) out[10] = (float)am;
        for (int j = 11; j < out_size; j++) out[j] = 0.f;
    }
}

// ---------------- host orchestration ----------------
struct Ptrs {
    float *h, *xln, *qkv, *QL, *KL, *A3;
    float *S2, *XZ, *T1, *T2, *Z, *Z2, *T, *U, *attn, *y, *scal;
};

static void get_ptrs(Ptrs& P) {
    cudaGetSymbolAddress((void**)&P.h,    g_h);
    cudaGetSymbolAddress((void**)&P.xln,  g_xln);
    cudaGetSymbolAddress((void**)&P.qkv,  g_qkv);
    cudaGetSymbolAddress((void**)&P.QL,   g_QL);
    cudaGetSymbolAddress((void**)&P.KL,   g_KL);
    cudaGetSymbolAddress((void**)&P.A3,   g_A3);
    cudaGetSymbolAddress((void**)&P.S2,   g_S2);
    cudaGetSymbolAddress((void**)&P.XZ,   g_XZ);
    cudaGetSymbolAddress((void**)&P.T1,   g_T1);
    cudaGetSymbolAddress((void**)&P.T2,   g_T2);
    cudaGetSymbolAddress((void**)&P.Z,    g_Zb);
    cudaGetSymbolAddress((void**)&P.Z2,   g_Z2b);
    cudaGetSymbolAddress((void**)&P.T,    g_Tb);
    cudaGetSymbolAddress((void**)&P.U,    g_Ub);
    cudaGetSymbolAddress((void**)&P.attn, g_attn);
    cudaGetSymbolAddress((void**)&P.y,    g_y);
    cudaGetSymbolAddress((void**)&P.scal, g_scal);
}

#define MMA_BIG_NN  gemm_mma<128,128,64,32,false,false>
#define MMA_BIG_NT  gemm_mma<128,128,64,32,true ,false>
#define MMA_SM_NN   gemm_mma<64,64,32,32,false,false>
#define MMA_SM_NT   gemm_mma<64,64,32,32,true ,false>
#define MMA_SM_SPK  gemm_mma<64,64,32,32,false,true >

static inline dim3 grid128(int M, int N, int batch) {
    return dim3(N / 128, (M + 127) / 128, batch);
}
static inline dim3 grid64(int M, int N, int batch) {
    return dim3(N / 64, (M + 63) / 64, batch);
}

static void run_attention(const Ptrs& P, const float* lng, const float* lnb,
                          const float* Wqkv, const float* Wout, const float* bout,
                          const float* resw)
{
    const long sLnd = (long)NL*DH;
    const long sQ   = (long)NL*NL;
    const float QS = 0.125f;

    const float* Kv = P.qkv + DIM;
    const float* Vv = P.qkv + 2*DIM;

    ln_pad<<<NPAD, 256>>>(P.h, P.xln, lng, lnb);
    MMA_BIG_NN<<<grid128(NPAD, 3*DIM, 1), 256>>>(
        P.xln, Wqkv, P.qkv, NPAD, 3*DIM, DIM, DIM, 3*DIM, 3*DIM,
        0, 0, 0, 1.f, 0.f, 0.f, nullptr, 0);
    res_conv2<<<NPAD/8, 512>>>(P.attn, P.qkv, resw);
    landmarks_k<<<(HEADS*NL*DH + 255)/256, 256>>>(P.qkv, P.QL, P.KL);
    MMA_SM_NT<<<grid64(NL, NL, HEADS), 128>>>(
        P.QL, P.KL, P.S2, NL, NL, DH, DH, DH, NL,
        sLnd, sLnd, sQ, QS, 0.f, 0.f, nullptr, 0);
    softmax256<<<HEADS*NL, 128>>>(P.S2);
    pinv_persist<<<PBLOCKS, 128>>>(P.S2, P.Z, P.Z2, P.XZ, P.T1, P.T2, P.scal);
    MMA_BIG_NT<<<grid128(NL, NPAD, HEADS), 256>>>(
        P.QL, Kv, P.A3, NL, NPAD, DH, DH, QKVD, NPAD,
        sLnd, (long)DH, (long)NL*NPAD, QS, 0.f, 0.f, nullptr, 0);
    softmax_wide<<<HEADS*NL, 256>>>(P.A3);
    zero_kernel<<<(HEADS*NL*DH + 255)/256, 256>>>(P.T, (long)HEADS*NL*DH);
    MMA_SM_SPK<<<grid64(NL, DH, HEADS*NSPLIT), 128>>>(
        P.A3, Vv, P.T, NL, DH, NPAD, NPAD, QKVD, DH,
        (long)NL*NPAD, (long)DH, sLnd, 1.f, 0.f, 0.f, nullptr, 0);
    MMA_SM_NN<<<grid64(NL, DH, HEADS), 128>>>(
        P.Z, P.T, P.U, NL, DH, NL, NL, DH, DH,
        sQ, sLnd, sLnd, 1.f, 0.f, 0.f, nullptr, 0);
    attn1_fused<<<dim3(NPAD/64, HEADS), 128, A1_SMEMB>>>(P.qkv, P.KL, P.U, P.attn);
    MMA_BIG_NN<<<grid128(NPAD, DIM, 1), 256>>>(
        P.attn, Wout, P.h, NPAD, DIM, DIM, DIM, DIM, DIM,
        0, 0, 0, 1.f, 0.f, 0.f, bout, 2);
}

extern "C" void kernel_launch(void* const* d_in, const int* in_sizes, int n_in,
                              void* d_out, int out_size)
{
    const float* data      = (const float*)d_in[0];
    const float* W_fc1     = (const float*)d_in[1];
    const float* b_fc1     = (const float*)d_in[2];
    const float* cls_token = (const float*)d_in[3];
    const float* ln1_g     = (const float*)d_in[4];
    const float* ln1_b     = (const float*)d_in[5];
    const float* qkv1      = (const float*)d_in[6];
    const float* out1_w    = (const float*)d_in[7];
    const float* out1_b    = (const float*)d_in[8];
    const float* res1      = (const float*)d_in[9];
    const float* w7        = (const float*)d_in[10];
    const float* b7        = (const float*)d_in[11];
    const float* w5        = (const float*)d_in[12];
    const float* b5        = (const float*)d_in[13];
    const float* w3        = (const float*)d_in[14];
    const float* b3        = (const float*)d_in[15];
    const float* ln2_g     = (const float*)d_in[16];
    const float* ln2_b     = (const float*)d_in[17];
    const float* qkv2      = (const float*)d_in[18];
    const float* out2_w    = (const float*)d_in[19];
    const float* out2_b    = (const float*)d_in[20];
    const float* res2      = (const float*)d_in[21];
    const float* norm_g    = (const float*)d_in[22];
    const float* norm_b    = (const float*)d_in[23];
    const float* W_fc2     = (const float*)d_in[24];
    const float* b_fc2     = (const float*)d_in[25];

    Ptrs P;
    get_ptrs(P);

    cudaFuncSetAttribute(attn1_fused,
        cudaFuncAttributeMaxDynamicSharedMemorySize, A1_SMEMB);

    set_cls<<<1, DIM>>>(P.h, cls_token);
    MMA_BIG_NN<<<grid128(15000, DIM, 1), 256>>>(
        data, W_fc1, P.h + DIM, 15000, DIM, 1024, 1024, DIM, DIM,
        0, 0, 0, 1.f, 0.f, 0.f, b_fc1, 1);
    dup_rows<<<(129*DIM + 255)/256, 256>>>(P.h);

    run_attention(P, ln1_g, ln1_b, qkv1, out1_w, out1_b, res1);

    ppeg2<<<dim3((NPIX + PPP - 1)/PPP, DIM/128), 128>>>(
        P.h, P.y, w7, b7, w5, b5, w3, b3);
    ppeg_copyback<<<(int)(((long)NPIX*DIM + 255)/256), 256>>>(P.h, P.y);

    run_attention(P, ln2_g, ln2_b, qkv2, out2_w, out2_b, res2);

    final_head<<<1, DIM>>>(P.h, norm_g, norm_b, W_fc2, b_fc2, (float*)d_out, out_size);
}

// round 16
// speedup vs baseline: 1.0751x; 1.0327x over previous
#include <cuda_runtime.h>
#include <math.h>
#include <stdint.h>

#define HEADS 8
#define DH    64
#define DIM   512
#define QKVD  1536
#define NTOK  15130
#define NPAD  15360
#define PADR  230
#define NL    256
#define LCH   60
#define IMGH  123
#define NPIX  15129
#define NSPLIT 16

// ---------------- static scratch (allocation-free rule) ----------------
__device__ __align__(16) float g_h   [NTOK*DIM];
__device__ __align__(16) float g_xln [NPAD*DIM];
__device__ __align__(16) float g_qkv [NPAD*3*DIM];
__device__ __align__(16) float g_QL  [HEADS*NL*DH];
__device__ __align__(16) float g_KL  [HEADS*NL*DH];
__device__ __align__(16) float g_A3  [HEADS*NL*NPAD];
__device__ __align__(16) float g_S2  [HEADS*NL*NL];
__device__ __align__(16) float g_XZ  [HEADS*NL*NL];
__device__ __align__(16) float g_T1  [HEADS*NL*NL];
__device__ __align__(16) float g_T2  [HEADS*NL*NL];
__device__ __align__(16) float g_Zb  [HEADS*NL*NL];
__device__ __align__(16) float g_Z2b [HEADS*NL*NL];
__device__ __align__(16) float g_Tb  [HEADS*NL*DH];
__device__ __align__(16) float g_Ub  [HEADS*NL*DH];
__device__ __align__(16) float g_attn[NPAD*DIM];
__device__ __align__(16) float g_y   [NPAD*DIM];
__device__ float g_scal[2];

// ================= bf16 split primitives =================
__device__ __forceinline__ uint32_t pkbf(float x0, float x1) {
    uint32_t r;
    asm("cvt.rn.bf16x2.f32 %0, %1, %2;" : "=r"(r) : "f"(x1), "f"(x0));
    return r;
}
__device__ __forceinline__ float unlo(uint32_t p) {
    return __uint_as_float(p << 16);
}
__device__ __forceinline__ float unhi(uint32_t p) {
    return __uint_as_float(p & 0xFFFF0000u);
}
__device__ __forceinline__ void bsplit4(float4 v,
    uint32_t& h0, uint32_t& h1, uint32_t& l0, uint32_t& l1)
{
    h0 = pkbf(v.x, v.y);
    h1 = pkbf(v.z, v.w);
    l0 = pkbf(v.x - unlo(h0), v.y - unhi(h0));
    l1 = pkbf(v.z - unlo(h1), v.w - unhi(h1));
}
__device__ __forceinline__ void bsplit2(float x0, float x1, uint32_t& h, uint32_t& l) {
    h = pkbf(x0, x1);
    l = pkbf(x0 - unlo(h), x1 - unhi(h));
}
__device__ __forceinline__ void mma16(float* d,
    uint32_t a0, uint32_t a1, uint32_t a2, uint32_t a3,
    uint32_t b0, uint32_t b1)
{
    asm volatile("mma.sync.aligned.m16n8k16.row.col.f32.bf16.bf16.f32 "
        "{%0,%1,%2,%3},{%4,%5,%6,%7},{%8,%9},{%0,%1,%2,%3};"
        : "+f"(d[0]), "+f"(d[1]), "+f"(d[2]), "+f"(d[3])
        : "r"(a0), "r"(a1), "r"(a2), "r"(a3), "r"(b0), "r"(b1));
}
__device__ __forceinline__ void mma16_split(float* acc,
    const uint32_t* Ah, const uint32_t* Al, const uint32_t* Bh, const uint32_t* Bl)
{
    mma16(acc, Ah[0],Ah[1],Ah[2],Ah[3], Bh[0],Bh[1]);
    mma16(acc, Ah[0],Ah[1],Ah[2],Ah[3], Bl[0],Bl[1]);
    mma16(acc, Al[0],Al[1],Al[2],Al[3], Bh[0],Bh[1]);
}

#define PADS 4

// ================= generic bf16-split GEMM (batched, NN/NT, split-K) ============
// (R9-verified layout: k-pair-major packed tiles, scalar fragment LDS)
template<int BM, int BN, int WM, int WN, bool NT, bool SPLITK>
__global__ void __launch_bounds__((BM/WM)*(BN/WN)*32)
gemm_mma(const float* __restrict__ A, const float* __restrict__ B,
         float* __restrict__ C,
         int M, int N, int K, int lda, int ldb, int ldc,
         long sA, long sB, long sC,
         float alpha, float beta_diag, float gammaA,
         const float* __restrict__ bias, int mode)
{
    constexpr int NWARP = (BM/WM)*(BN/WN);
    constexpr int T = NWARP * 32;
    constexpr int NWN = BN / WN;
    constexpr int MT = WM / 16, NTL = WN / 8;
    static_assert(T == 8 * (BN / 4), "B-NN loader mapping requires T == 2*BN");

    int z = blockIdx.z;
    int kbeg = 0, kend = K;
    if (SPLITK) {
        int batch = z / NSPLIT, split = z % NSPLIT;
        A += (long)batch * sA; B += (long)batch * sB; C += (long)batch * sC;
        int chunk = K / NSPLIT;
        kbeg = split * chunk; kend = kbeg + chunk;
    } else {
        A += (long)z * sA; B += (long)z * sB; C += (long)z * sC;
    }

    __shared__ __align__(16) uint32_t sAh[2][8][BM + PADS];
    __shared__ __align__(16) uint32_t sAl[2][8][BM + PADS];
    __shared__ __align__(16) uint32_t sBh[2][8][BN + PADS];
    __shared__ __align__(16) uint32_t sBl[2][8][BN + PADS];

    const int tid = threadIdx.x;
    const int wid = tid >> 5, lane = tid & 31;
    const int g = lane >> 2, t = lane & 3;
    const int row0 = blockIdx.y * BM;
    const int col0 = blockIdx.x * BN;
    const int wm0 = (wid / NWN) * WM;
    const int wn0 = (wid % NWN) * WN;

    float4 ra[2], rb[2];

    auto load_g = [&](int k0) {
        #pragma unroll
        for (int it = 0; it < 2; it++) {
            int i = tid + it * T;
            int m = i >> 2, kq = (i & 3) * 4;
            int gm = row0 + m;
            ra[it] = make_float4(0.f, 0.f, 0.f, 0.f);
            if (gm < M) ra[it] = *(const float4*)&A[(long)gm * lda + k0 + kq];
        }
        if (!NT) {
            int k2 = tid / (BN / 4), ng = (tid % (BN / 4)) * 4;
            rb[0] = *(const float4*)&B[(long)(k0 + 2*k2)     * ldb + col0 + ng];
            rb[1] = *(const float4*)&B[(long)(k0 + 2*k2 + 1) * ldb + col0 + ng];
        } else {
            #pragma unroll
            for (int it = 0; it < 2; it++) {
                int i = tid + it * T;
                int n = i >> 2, kq = (i & 3) * 4;
                rb[it] = make_float4(0.f, 0.f, 0.f, 0.f);
                if (col0 + n < N)
                    rb[it] = *(const float4*)&B[(long)(col0 + n) * ldb + k0 + kq];
            }
        }
    };
    auto store_s = [&](int buf) {
        #pragma unroll
        for (int it = 0; it < 2; it++) {
            int i = tid + it * T;
            int m = i >> 2, kp = (i & 3) * 2;
            uint32_t h0, h1, l0, l1;
            bsplit4(ra[it], h0, h1, l0, l1);
            sAh[buf][kp][m]     = h0;
            sAh[buf][kp + 1][m] = h1;
            sAl[buf][kp][m]     = l0;
            sAl[buf][kp + 1][m] = l1;
        }
        if (!NT) {
            int k2 = tid / (BN / 4), ng = (tid % (BN / 4)) * 4;
            const float* v0 = &rb[0].x;
            const float* v1 = &rb[1].x;
            uint32_t hh[4], ll[4];
            #pragma unroll
            for (int q = 0; q < 4; q++) {
                uint32_t h = pkbf(v0[q], v1[q]);
                hh[q] = h;
                ll[q] = pkbf(v0[q] - unlo(h), v1[q] - unhi(h));
            }
            *(uint4*)&sBh[buf][k2][ng] = *(uint4*)hh;
            *(uint4*)&sBl[buf][k2][ng] = *(uint4*)ll;
        } else {
            #pragma unroll
            for (int it = 0; it < 2; it++) {
                int i = tid + it * T;
                int n = i >> 2, kp = (i & 3) * 2;
                uint32_t h0, h1, l0, l1;
                bsplit4(rb[it], h0, h1, l0, l1);
                sBh[buf][kp][n]     = h0;
                sBh[buf][kp + 1][n] = h1;
                sBl[buf][kp][n]     = l0;
                sBl[buf][kp + 1][n] = l1;
            }
        }
    };

    float acc[MT][NTL][4];
    #pragma unroll
    for (int i = 0; i < MT; i++)
        #pragma unroll
        for (int j = 0; j < NTL; j++)
            #pragma unroll
            for (int q = 0; q < 4; q++) acc[i][j][q] = 0.f;

    const int ntiles = (kend - kbeg) / 16;
    load_g(kbeg);
    store_s(0);
    __syncthreads();

    for (int kt = 0; kt < ntiles; kt++) {
        if (kt + 1 < ntiles) load_g(kbeg + (kt + 1) * 16);
        int buf = kt & 1;
        {
            uint32_t Ahf[MT][4], Alf[MT][4], Bhf[NTL][2], Blf[NTL][2];
            #pragma unroll
            for (int mt = 0; mt < MT; mt++) {
                int mb = wm0 + mt * 16 + g;
                Ahf[mt][0] = sAh[buf][t    ][mb];
                Ahf[mt][1] = sAh[buf][t    ][mb + 8];
                Ahf[mt][2] = sAh[buf][t + 4][mb];
                Ahf[mt][3] = sAh[buf][t + 4][mb + 8];
                Alf[mt][0] = sAl[buf][t    ][mb];
                Alf[mt][1] = sAl[buf][t    ][mb + 8];
                Alf[mt][2] = sAl[buf][t + 4][mb];
                Alf[mt][3] = sAl[buf][t + 4][mb + 8];
            }
            #pragma unroll
            for (int nt = 0; nt < NTL; nt++) {
                int nb = wn0 + nt * 8 + g;
                Bhf[nt][0] = sBh[buf][t    ][nb];
                Bhf[nt][1] = sBh[buf][t + 4][nb];
                Blf[nt][0] = sBl[buf][t    ][nb];
                Blf[nt][1] = sBl[buf][t + 4][nb];
            }
            #pragma unroll
            for (int mt = 0; mt < MT; mt++)
                #pragma unroll
                for (int nt = 0; nt < NTL; nt++)
                    mma16_split(acc[mt][nt], Ahf[mt], Alf[mt], Bhf[nt], Blf[nt]);
        }
        if (kt + 1 < ntiles) {
            store_s((kt + 1) & 1);
            __syncthreads();
        }
    }

    auto emit = [&](int r, int c, float v0, float v1) {
        if (r >= M) return;
        v0 *= alpha; v1 *= alpha;
        if (bias) { v0 += bias[c]; v1 += bias[c + 1]; }
        if (beta_diag != 0.f) {
            if (r == c)     v0 += beta_diag;
            if (r == c + 1) v1 += beta_diag;
        }
        if (gammaA != 0.f) {
            v0 += gammaA * A[(long)r * lda + c];
            v1 += gammaA * A[(long)r * lda + c + 1];
        }
        if (mode == 1) { v0 = fmaxf(v0, 0.f); v1 = fmaxf(v1, 0.f); }
        if (SPLITK) {
            atomicAdd(&C[(long)r * ldc + c], v0);
            atomicAdd(&C[(long)r * ldc + c + 1], v1);
        } else if (mode == 2) {
            if (r >= PADR) {
                float2* dst = (float2*)&C[(long)(r - PADR) * ldc + c];
                float2 o = *dst;
                o.x += v0; o.y += v1;
                *dst = o;
            }
        } else {
            *(float2*)&C[(long)r * ldc + c] = make_float2(v0, v1);
        }
    };
    #pragma unroll
    for (int mt = 0; mt < MT; mt++)
        #pragma unroll
        for (int nt = 0; nt < NTL; nt++) {
            int r = row0 + wm0 + mt * 16 + g;
            int c = col0 + wn0 + nt * 8 + 2 * t;
            emit(r,     c, acc[mt][nt][0], acc[mt][nt][1]);
            emit(r + 8, c, acc[mt][nt][2], acc[mt][nt][3]);
        }
}

// ================= pinv helper kernels (R4-verified lineage) =================
__device__ __forceinline__ void atomicMaxFloatPos(float* addr, float v) {
    atomicMax((int*)addr, __float_as_int(v));
}

__global__ void zero_kernel(float* p, long n) {
    long i = (long)blockIdx.x * blockDim.x + threadIdx.x;
    if (i < n) p[i] = 0.f;
}

__global__ void pinv_scalars(const float* __restrict__ A2, float* __restrict__ scal) {
    int hb = blockIdx.x;
    int h = hb / NL, i = hb % NL;
    int mode = blockIdx.y;     // 0: row-sums, 1: col-sums
    const float* base = A2 + (long)h*NL*NL;
    float s = 0.f;
    if (mode == 0) { for (int j = threadIdx.x; j < NL; j += blockDim.x) s += fabsf(base[(long)i*NL + j]); }
    else           { for (int j = threadIdx.x; j < NL; j += blockDim.x) s += fabsf(base[(long)j*NL + i]); }
    #pragma unroll
    for (int o = 16; o; o >>= 1) s += __shfl_xor_sync(~0u, s, o);
    __shared__ float red[8];
    if ((threadIdx.x & 31) == 0) red[threadIdx.x >> 5] = s;
    __syncthreads();
    if (threadIdx.x == 0) {
        float tot = 0.f;
        for (int w = 0; w < blockDim.x / 32; w++) tot += red[w];
        atomicMaxFloatPos(&scal[mode], tot);
    }
}

__global__ void zinit(const float* __restrict__ A2, float* __restrict__ Z,
                      const float* __restrict__ scal)
{
    int idx = blockIdx.x * blockDim.x + threadIdx.x;
    if (idx >= HEADS*NL*NL) return;
    int h = idx / (NL*NL);
    int r = (idx / NL) % NL;
    int c = idx % NL;
    float denom = scal[0] * scal[1];
    Z[idx] = A2[(long)h*NL*NL + (long)c*NL + r] / denom;
}

// ================= fused a1 attention (bf16 split): attn += softmax(P)@U ========
#define A1_AQH   0
#define A1_AQL   (32*68)
#define A1_BKH   (2*32*68)
#define A1_BKL   (2*32*68 + 32*260)
#define A1_PH    0
#define A1_PL    (128*68)
#define A1_ST    20992
#define A1_UH    37632
#define A1_UL    (37632 + 128*68)
#define A1_RINV  55040
#define A1_SMEMB (55104*4)

__global__ void __launch_bounds__(128) attn1_fused(
    const float* __restrict__ qkv, const float* __restrict__ KL,
    const float* __restrict__ U, float* __restrict__ attn)
{
    extern __shared__ float sm[];
    uint32_t* AQh = (uint32_t*)sm + A1_AQH;
    uint32_t* AQl = (uint32_t*)sm + A1_AQL;
    uint32_t* BKh = (uint32_t*)sm + A1_BKH;
    uint32_t* BKl = (uint32_t*)sm + A1_BKL;
    uint32_t* Ph  = (uint32_t*)sm + A1_PH;
    uint32_t* Pl  = (uint32_t*)sm + A1_PL;
    float*    ST  = sm + A1_ST;
    uint32_t* Uh  = (uint32_t*)sm + A1_UH;
    uint32_t* Ul  = (uint32_t*)sm + A1_UL;
    float*    rinv= sm + A1_RINV;

    const int tid = threadIdx.x;
    const int wid = tid >> 5, lane = tid & 31;
    const int g = lane >> 2, t = lane & 3;
    const int h = blockIdx.y;
    const int row0 = blockIdx.x * 64;
    const float* Qg  = qkv + h * DH;
    const float* KLh = KL + (long)h * NL * DH;
    const float* Ug  = U  + (long)h * NL * DH;

    #pragma unroll
    for (int l = 0; l < 8; l++) {
        int i = tid + l * 128;
        int m = i >> 4, kq = (i & 15) * 4;
        float4 v = *(const float4*)&Qg[(long)(row0 + m) * QKVD + kq];
        uint32_t h0, h1, l0, l1;
        bsplit4(v, h0, h1, l0, l1);
        int kp = kq >> 1;
        AQh[kp*68 + m] = h0; AQh[(kp+1)*68 + m] = h1;
        AQl[kp*68 + m] = l0; AQl[(kp+1)*68 + m] = l1;
    }
    #pragma unroll
    for (int l = 0; l < 32; l++) {
        int i = tid + l * 128;
        int n = i >> 4, kq = (i & 15) * 4;
        float4 v = *(const float4*)&KLh[n * 64 + kq];
        uint32_t h0, h1, l0, l1;
        bsplit4(v, h0, h1, l0, l1);
        int kp = kq >> 1;
        BKh[kp*260 + n] = h0; BKh[(kp+1)*260 + n] = h1;
        BKl[kp*260 + n] = l0; BKl[(kp+1)*260 + n] = l1;
    }
    #pragma unroll
    for (int l = 0; l < 16; l++) {
        int i = tid + l * 128;
        int kp = i >> 4, n4 = (i & 15) * 4;
        float4 v0 = *(const float4*)&Ug[(long)(2*kp)     * 64 + n4];
        float4 v1 = *(const float4*)&Ug[(long)(2*kp + 1) * 64 + n4];
        const float* p0 = &v0.x;
        const float* p1 = &v1.x;
        uint32_t hh[4], ll[4];
        #pragma unroll
        for (int q = 0; q < 4; q++) {
            uint32_t hq = pkbf(p0[q], p1[q]);
            hh[q] = hq;
            ll[q] = pkbf(p0[q] - unlo(hq), p1[q] - unhi(hq));
        }
        *(uint4*)&Uh[kp*68 + n4] = *(uint4*)hh;
        *(uint4*)&Ul[kp*68 + n4] = *(uint4*)ll;
    }
    __syncthreads();

    const int wm0 = (wid >> 1) * 32;
    const int wn1 = (wid & 1) * 128;
    {
        float acc1[2][16][4] = {};
        #pragma unroll
        for (int k16 = 0; k16 < 4; k16++) {
            int kb = k16 * 8;
            uint32_t Ahf[2][4], Alf[2][4];
            #pragma unroll
            for (int mt = 0; mt < 2; mt++) {
                int mb = wm0 + mt * 16 + g;
                Ahf[mt][0] = AQh[(kb + t    )*68 + mb];
                Ahf[mt][1] = AQh[(kb + t    )*68 + mb + 8];
                Ahf[mt][2] = AQh[(kb + t + 4)*68 + mb];
                Ahf[mt][3] = AQh[(kb + t + 4)*68 + mb + 8];
                Alf[mt][0] = AQl[(kb + t    )*68 + mb];
                Alf[mt][1] = AQl[(kb + t    )*68 + mb + 8];
                Alf[mt][2] = AQl[(kb + t + 4)*68 + mb];
                Alf[mt][3] = AQl[(kb + t + 4)*68 + mb + 8];
            }
            #pragma unroll
            for (int nt = 0; nt < 16; nt++) {
                int nb = wn1 + nt * 8 + g;
                uint32_t Bhf[2], Blf[2];
                Bhf[0] = BKh[(kb + t    )*260 + nb];
                Bhf[1] = BKh[(kb + t + 4)*260 + nb];
                Blf[0] = BKl[(kb + t    )*260 + nb];
                Blf[1] = BKl[(kb + t + 4)*260 + nb];
                mma16_split(acc1[0][nt], Ahf[0], Alf[0], Bhf, Blf);
                mma16_split(acc1[1][nt], Ahf[1], Alf[1], Bhf, Blf);
            }
        }
        #pragma unroll
        for (int mt = 0; mt < 2; mt++)
            #pragma unroll
            for (int nt = 0; nt < 16; nt++) {
                int r = wm0 + mt * 16 + g;
                int c = wn1 + nt * 8 + 2 * t;
                ST[c*65 + r]       = 0.125f * acc1[mt][nt][0];
                ST[(c+1)*65 + r]   = 0.125f * acc1[mt][nt][1];
                ST[c*65 + r+8]     = 0.125f * acc1[mt][nt][2];
                ST[(c+1)*65 + r+8] = 0.125f * acc1[mt][nt][3];
            }
    }
    __syncthreads();

    {
        int r = tid >> 1, half = tid & 1;
        int j0 = half * 128;
        float m = -1e30f;
        #pragma unroll 8
        for (int j = j0; j < j0 + 128; j++) m = fmaxf(m, ST[j*65 + r]);
        m = fmaxf(m, __shfl_xor_sync(~0u, m, 1));
        float s = 0.f;
        #pragma unroll 8
        for (int j = j0; j < j0 + 128; j++) {
            float e = __expf(ST[j*65 + r] - m);
            ST[j*65 + r] = e;
            s += e;
        }
        s += __shfl_xor_sync(~0u, s, 1);
        if (half == 0) rinv[r] = 1.f / s;
    }
    __syncthreads();

    #pragma unroll
    for (int l = 0; l < 64; l++) {
        int i = tid + l * 128;
        int kp = i >> 6, m = i & 63;
        float x0 = ST[(2*kp)     * 65 + m];
        float x1 = ST[(2*kp + 1) * 65 + m];
        uint32_t hq, lq;
        bsplit2(x0, x1, hq, lq);
        Ph[kp*68 + m] = hq;
        Pl[kp*68 + m] = lq;
    }
    __syncthreads();

    {
        const int wn2 = (wid & 1) * 32;
        float acc2[2][4][4] = {};
        #pragma unroll 4
        for (int k16 = 0; k16 < 16; k16++) {
            int kb = k16 * 8;
            uint32_t Ahf[2][4], Alf[2][4], Bhf[4][2], Blf[4][2];
            #pragma unroll
            for (int mt = 0; mt < 2; mt++) {
                int mb = wm0 + mt * 16 + g;
                Ahf[mt][0] = Ph[(kb + t    )*68 + mb];
                Ahf[mt][1] = Ph[(kb + t    )*68 + mb + 8];
                Ahf[mt][2] = Ph[(kb + t + 4)*68 + mb];
                Ahf[mt][3] = Ph[(kb + t + 4)*68 + mb + 8];
                Alf[mt][0] = Pl[(kb + t    )*68 + mb];
                Alf[mt][1] = Pl[(kb + t    )*68 + mb + 8];
                Alf[mt][2] = Pl[(kb + t + 4)*68 + mb];
                Alf[mt][3] = Pl[(kb + t + 4)*68 + mb + 8];
            }
            #pragma unroll
            for (int nt = 0; nt < 4; nt++) {
                int nb = wn2 + nt * 8 + g;
                Bhf[nt][0] = Uh[(kb + t    )*68 + nb];
                Bhf[nt][1] = Uh[(kb + t + 4)*68 + nb];
                Blf[nt][0] = Ul[(kb + t    )*68 + nb];
                Blf[nt][1] = Ul[(kb + t + 4)*68 + nb];
            }
            #pragma unroll
            for (int mt = 0; mt < 2; mt++)
                #pragma unroll
                for (int nt = 0; nt < 4; nt++)
                    mma16_split(acc2[mt][nt], Ahf[mt], Alf[mt], Bhf[nt], Blf[nt]);
        }
        #pragma unroll
        for (int mt = 0; mt < 2; mt++)
            #pragma unroll
            for (int nt = 0; nt < 4; nt++) {
                int rl = wm0 + mt * 16 + g;
                int c = h * DH + wn2 + nt * 8 + 2 * t;
                float i0 = rinv[rl], i1 = rinv[rl + 8];
                float2* d0 = (float2*)&attn[(long)(row0 + rl) * DIM + c];
                float2 o0 = *d0;
                o0.x += acc2[mt][nt][0] * i0;
                o0.y += acc2[mt][nt][1] * i0;
                *d0 = o0;
                float2* d1 = (float2*)&attn[(long)(row0 + rl + 8) * DIM + c];
                float2 o1 = *d1;
                o1.x += acc2[mt][nt][2] * i1;
                o1.y += acc2[mt][nt][3] * i1;
                *d1 = o1;
            }
    }
}

// ---------------- misc kernels ----------------
__global__ void set_cls(float* h, const float* __restrict__ cls) {
    h[threadIdx.x] = cls[threadIdx.x];
}

// copy post-block-1 cls row h[0..DIM) into y[0..DIM)
__global__ void copy_cls(float* __restrict__ y, const float* __restrict__ h) {
    y[threadIdx.x] = h[threadIdx.x];
}

__global__ void dup_rows(float* h) {
    int i = blockIdx.x * blockDim.x + threadIdx.x;
    if (i < 129*DIM) {
        int t = i / DIM, c = i % DIM;
        h[(long)(15001 + t)*DIM + c] = h[(long)(1 + t)*DIM + c];
    }
}

__global__ void __launch_bounds__(256) ln_pad(
    const float* __restrict__ h, float* __restrict__ xo,
    const float* __restrict__ g, const float* __restrict__ b)
{
    int row = blockIdx.x, tid = threadIdx.x;
    float2* out2 = (float2*)(xo + (long)row * DIM);
    if (row < PADR) { out2[tid] = make_float2(0.f, 0.f); return; }
    const float2 xv = ((const float2*)(h + (long)(row - PADR) * DIM))[tid];
    __shared__ float sm1[8], sm2[8];
    float s = xv.x + xv.y;
    #pragma unroll
    for (int o = 16; o; o >>= 1) s += __shfl_xor_sync(~0u, s, o);
    if ((tid & 31) == 0) sm1[tid >> 5] = s;
    __syncthreads();
    float mu = (sm1[0]+sm1[1]+sm1[2]+sm1[3]+sm1[4]+sm1[5]+sm1[6]+sm1[7]) * (1.f/DIM);
    float d0 = xv.x - mu, d1 = xv.y - mu;
    float v = d0*d0 + d1*d1;
    #pragma unroll
    for (int o = 16; o; o >>= 1) v += __shfl_xor_sync(~0u, v, o);
    if ((tid & 31) == 0) sm2[tid >> 5] = v;
    __syncthreads();
    float var = (sm2[0]+sm2[1]+sm2[2]+sm2[3]+sm2[4]+sm2[5]+sm2[6]+sm2[7]) * (1.f/DIM);
    float rstd = rsqrtf(var + 1e-5f);
    float2 gg = ((const float2*)g)[tid];
    float2 bb = ((const float2*)b)[tid];
    out2[tid] = make_float2(d0*rstd*gg.x + bb.x, d1*rstd*gg.y + bb.y);
}

__global__ void landmarks_k(const float* __restrict__ qkv,
                            float* __restrict__ QL, float* __restrict__ KL)
{
    int idx = blockIdx.x * blockDim.x + threadIdx.x;
    if (idx >= HEADS*NL*DH) return;
    int h = idx / (NL*DH);
    int j = (idx / DH) % NL;
    int d = idx % DH;
    const float* qb = qkv + (long)(j*LCH)*QKVD + h*DH + d;
    const float* kb = qb + DIM;
    float sq = 0.f, sk = 0.f;
    for (int i = 0; i < LCH; i++) { sq += qb[(long)i*QKVD]; sk += kb[(long)i*QKVD]; }
    QL[idx] = sq * (1.f/LCH);
    KL[idx] = sk * (1.f/LCH);
}

__global__ void __launch_bounds__(128) softmax256(float* __restrict__ X) {
    long r = blockIdx.x;
    float2* x = (float2*)(X + r * (long)NL);
    int tid = threadIdx.x;
    float2 v = x[tid];
    __shared__ float sm[4];
    float m = fmaxf(v.x, v.y);
    #pragma unroll
    for (int o = 16; o; o >>= 1) m = fmaxf(m, __shfl_xor_sync(~0u, m, o));
    if ((tid & 31) == 0) sm[tid >> 5] = m;
    __syncthreads();
    m = fmaxf(fmaxf(sm[0], sm[1]), fmaxf(sm[2], sm[3]));
    __syncthreads();
    v.x = __expf(v.x - m); v.y = __expf(v.y - m);
    float s = v.x + v.y;
    #pragma unroll
    for (int o = 16; o; o >>= 1) s += __shfl_xor_sync(~0u, s, o);
    if ((tid & 31) == 0) sm[tid >> 5] = s;
    __syncthreads();
    float inv = 1.f / (sm[0]+sm[1]+sm[2]+sm[3]);
    x[tid] = make_float2(v.x * inv, v.y * inv);
}

__global__ void __launch_bounds__(256) softmax_wide(float* __restrict__ X) {
    long r = blockIdx.x;
    float* x = X + r * (long)NPAD;
    int tid = threadIdx.x;
    float4 v[15];
    #pragma unroll
    for (int i = 0; i < 15; i++) v[i] = *(float4*)&x[tid*4 + i*1024];
    __shared__ float sm[8];
    float m = -1e30f;
    #pragma unroll
    for (int i = 0; i < 15; i++)
        m = fmaxf(m, fmaxf(fmaxf(v[i].x, v[i].y), fmaxf(v[i].z, v[i].w)));
    #pragma unroll
    for (int o = 16; o; o >>= 1) m = fmaxf(m, __shfl_xor_sync(~0u, m, o));
    if ((tid & 31) == 0) sm[tid >> 5] = m;
    __syncthreads();
    m = fmaxf(fmaxf(fmaxf(sm[0],sm[1]),fmaxf(sm[2],sm[3])),
              fmaxf(fmaxf(sm[4],sm[5]),fmaxf(sm[6],sm[7])));
    __syncthreads();
    float s = 0.f;
    #pragma unroll
    for (int i = 0; i < 15; i++) {
        v[i].x = __expf(v[i].x - m); v[i].y = __expf(v[i].y - m);
        v[i].z = __expf(v[i].z - m); v[i].w = __expf(v[i].w - m);
        s += v[i].x + v[i].y + v[i].z + v[i].w;
    }
    #pragma unroll
    for (int o = 16; o; o >>= 1) s += __shfl_xor_sync(~0u, s, o);
    if ((tid & 31) == 0) sm[tid >> 5] = s;
    __syncthreads();
    float inv = 1.f / (sm[0]+sm[1]+sm[2]+sm[3]+sm[4]+sm[5]+sm[6]+sm[7]);
    #pragma unroll
    for (int i = 0; i < 15; i++) {
        v[i].x *= inv; v[i].y *= inv; v[i].z *= inv; v[i].w *= inv;
        *(float4*)&x[tid*4 + i*1024] = v[i];
    }
}

__global__ void __launch_bounds__(512) res_conv2(
    float* __restrict__ attn, const float* __restrict__ qkv,
    const float* __restrict__ w)
{
    int t0 = blockIdx.x * 8;
    int ch = threadIdx.x;
    int h = ch >> 6;
    float wk[33];
    #pragma unroll
    for (int k = 0; k < 33; k++) wk[k] = w[h*33 + k];
    float v[40];
    #pragma unroll
    for (int j = 0; j < 40; j++) {
        int tt = t0 + j - 16;
        v[j] = (tt >= 0 && tt < NPAD) ? qkv[(long)tt*QKVD + 2*DIM + ch] : 0.f;
    }
    #pragma unroll
    for (int j = 0; j < 8; j++) {
        float s = 0.f;
        #pragma unroll
        for (int k = 0; k < 33; k++) s += wk[k] * v[j + k];
        attn[(long)(t0 + j)*DIM + ch] = s;
    }
}

// PPEG v2 (R9-verified); writes features directly at out (= y + DIM)
#define PPP 16
__global__ void __launch_bounds__(128) ppeg2(
    const float* __restrict__ h, float* __restrict__ out,
    const float* __restrict__ w7, const float* __restrict__ b7,
    const float* __restrict__ w5, const float* __restrict__ b5,
    const float* __restrict__ w3, const float* __restrict__ b3)
{
    __shared__ float wc[49][128];
    int tid = threadIdx.x;
    int ch = blockIdx.y * 128 + tid;
    #pragma unroll
    for (int k = 0; k < 49; k++) {
        int dy = k / 7 - 3, dx = k % 7 - 3;
        float wv = w7[(long)ch*49 + k];
        if (dy >= -2 && dy <= 2 && dx >= -2 && dx <= 2)
            wv += w5[(long)ch*25 + (dy+2)*5 + (dx+2)];
        if (dy >= -1 && dy <= 1 && dx >= -1 && dx <= 1)
            wv += w3[(long)ch*9 + (dy+1)*3 + (dx+1)];
        if (k == 24) wv += 1.f;
        wc[k][tid] = wv;
    }
    float bias_c = b7[ch] + b5[ch] + b3[ch];
    __syncthreads();

    int p0 = blockIdx.x * PPP;
    #pragma unroll 1
    for (int pp = 0; pp < PPP; pp++) {
        int p = p0 + pp;
        if (p >= NPIX) break;
        int r = p / IMGH, c = p % IMGH;
        float acc = bias_c;
        if (r >= 3 && r < IMGH-3 && c >= 3 && c < IMGH-3) {
            #pragma unroll
            for (int k = 0; k < 49; k++) {
                int dy = k / 7 - 3, dx = k % 7 - 3;
                acc += h[(long)(1 + (r+dy)*IMGH + (c+dx))*DIM + ch] * wc[k][tid];
            }
        } else {
            #pragma unroll
            for (int k = 0; k < 49; k++) {
                int dy = k / 7 - 3, dx = k % 7 - 3;
                int rr = r + dy, cc = c + dx;
                if (rr >= 0 && rr < IMGH && cc >= 0 && cc < IMGH)
                    acc += h[(long)(1 + rr*IMGH + cc)*DIM + ch] * wc[k][tid];
            }
        }
        out[(long)p*DIM + ch] = acc;
    }
}

__global__ void final_head(const float* __restrict__ h, const float* __restrict__ g,
                           const float* __restrict__ b, const float* __restrict__ W,
                           const float* __restrict__ bias, float* __restrict__ out,
                           int out_size)
{
    __shared__ float red[512];
    __shared__ float xn[512];
    int tid = threadIdx.x;
    float x = h[tid];
    red[tid] = x; __syncthreads();
    for (int st = 256; st > 0; st >>= 1) {
        if (tid < st) red[tid] += red[tid+st];
        __syncthreads();
    }
    float mu = red[0] / DIM; __syncthreads();
    float d = x - mu;
    red[tid] = d*d; __syncthreads();
    for (int st = 256; st > 0; st >>= 1) {
        if (tid < st) red[tid] += red[tid+st];
        __syncthreads();
    }
    float rstd = rsqrtf(red[0]/DIM + 1e-5f); __syncthreads();
    xn[tid] = d*rstd*g[tid] + b[tid];
    __syncthreads();
    if (tid < 5) {
        float s = bias[tid];
        for (int c = 0; c < DIM; c++) s += xn[c] * W[c*5 + tid];
        red[tid] = s;
    }
    __syncthreads();
    if (tid == 0) {
        float lg[5], mx = -1e30f;
        for (int j = 0; j < 5; j++) { lg[j] = red[j]; mx = fmaxf(mx, lg[j]); }
        float se = 0.f, pr[5];
        for (int j = 0; j < 5; j++) { pr[j] = expf(lg[j]-mx); se += pr[j]; }
        int am = 0;
        for (int j = 1; j < 5; j++) if (lg[j] > lg[am]) am = j;
        for (int j = 0; j < 5; j++) {
            if (j < out_size)     out[j]     = lg[j];
            if (5 + j < out_size) out[5 + j] = pr[j]/se;
        }
        if (10 < out_size) out[10] = (float)am;
        for (int j = 11; j < out_size; j++) out[j] = 0.f;
    }
}

// ---------------- host orchestration ----------------
struct Ptrs {
    float *h, *xln, *qkv, *QL, *KL, *A3;
    float *S2, *XZ, *T1, *T2, *Z, *Z2, *T, *U, *attn, *y, *scal;
};

static void get_ptrs(Ptrs& P) {
    cudaGetSymbolAddress((void**)&P.h,    g_h);
    cudaGetSymbolAddress((void**)&P.xln,  g_xln);
    cudaGetSymbolAddress((void**)&P.qkv,  g_qkv);
    cudaGetSymbolAddress((void**)&P.QL,   g_QL);
    cudaGetSymbolAddress((void**)&P.KL,   g_KL);
    cudaGetSymbolAddress((void**)&P.A3,   g_A3);
    cudaGetSymbolAddress((void**)&P.S2,   g_S2);
    cudaGetSymbolAddress((void**)&P.XZ,   g_XZ);
    cudaGetSymbolAddress((void**)&P.T1,   g_T1);
    cudaGetSymbolAddress((void**)&P.T2,   g_T2);
    cudaGetSymbolAddress((void**)&P.Z,    g_Zb);
    cudaGetSymbolAddress((void**)&P.Z2,   g_Z2b);
    cudaGetSymbolAddress((void**)&P.T,    g_Tb);
    cudaGetSymbolAddress((void**)&P.U,    g_Ub);
    cudaGetSymbolAddress((void**)&P.attn, g_attn);
    cudaGetSymbolAddress((void**)&P.y,    g_y);
    cudaGetSymbolAddress((void**)&P.scal, g_scal);
}

#define MMA_BIG_NN  gemm_mma<128,128,64,32,false,false>
#define MMA_BIG_NT  gemm_mma<128,128,64,32,true ,false>
#define MMA_SM_NN   gemm_mma<64,64,32,32,false,false>
#define MMA_SM_NT   gemm_mma<64,64,32,32,true ,false>
#define MMA_SM_SPK  gemm_mma<64,64,32,32,false,true >

static inline dim3 grid128(int M, int N, int batch) {
    return dim3(N / 128, (M + 127) / 128, batch);
}
static inline dim3 grid64(int M, int N, int batch) {
    return dim3(N / 64, (M + 63) / 64, batch);
}

// hio: residual buffer for this block (read by ln_pad, accumulated by out-proj)
static void run_attention(const Ptrs& P, float* hio,
                          const float* lng, const float* lnb,
                          const float* Wqkv, const float* Wout, const float* bout,
                          const float* resw)
{
    const long sLnd = (long)NL*DH;
    const long sQ   = (long)NL*NL;
    const float QS = 0.125f;

    const float* Kv = P.qkv + DIM;
    const float* Vv = P.qkv + 2*DIM;

    ln_pad<<<NPAD, 256>>>(hio, P.xln, lng, lnb);
    MMA_BIG_NN<<<grid128(NPAD, 3*DIM, 1), 256>>>(
        P.xln, Wqkv, P.qkv, NPAD, 3*DIM, DIM, DIM, 3*DIM, 3*DIM,
        0, 0, 0, 1.f, 0.f, 0.f, nullptr, 0);
    res_conv2<<<NPAD/8, 512>>>(P.attn, P.qkv, resw);
    landmarks_k<<<(HEADS*NL*DH + 255)/256, 256>>>(P.qkv, P.QL, P.KL);
    MMA_SM_NT<<<grid64(NL, NL, HEADS), 128>>>(
        P.QL, P.KL, P.S2, NL, NL, DH, DH, DH, NL,
        sLnd, sLnd, sQ, QS, 0.f, 0.f, nullptr, 0);
    softmax256<<<HEADS*NL, 128>>>(P.S2);
    // pinv: graph-chained bf16 GEMM launches (barrier-free)
    zero_kernel<<<1, 32>>>(P.scal, 2);
    pinv_scalars<<<dim3(HEADS*NL, 2, 1), 256>>>(P.S2, P.scal);
    zinit<<<(HEADS*NL*NL + 255)/256, 256>>>(P.S2, P.Z, P.scal);
    for (int it = 0; it < 6; it++) {
        float* zin  = (it & 1) ? P.Z2 : P.Z;
        float* zout = (it & 1) ? P.Z  : P.Z2;
        MMA_SM_NN<<<grid64(NL, NL, HEADS), 128>>>(
            P.S2, zin, P.XZ, NL, NL, NL, NL, NL, NL, sQ, sQ, sQ,
            1.f, 0.f, 0.f, nullptr, 0);
        MMA_SM_NN<<<grid64(NL, NL, HEADS), 128>>>(
            P.XZ, P.XZ, P.T2, NL, NL, NL, NL, NL, NL, sQ, sQ, sQ,
            1.f, 15.f, -7.f, nullptr, 0);
        MMA_SM_NN<<<grid64(NL, NL, HEADS), 128>>>(
            P.XZ, P.T2, P.T1, NL, NL, NL, NL, NL, NL, sQ, sQ, sQ,
            -1.f, 13.f, 0.f, nullptr, 0);
        MMA_SM_NN<<<grid64(NL, NL, HEADS), 128>>>(
            zin, P.T1, zout, NL, NL, NL, NL, NL, NL, sQ, sQ, sQ,
            0.25f, 0.f, 0.f, nullptr, 0);
    }
    // result in P.Z after 6 iterations
    MMA_BIG_NT<<<grid128(NL, NPAD, HEADS), 256>>>(
        P.QL, Kv, P.A3, NL, NPAD, DH, DH, QKVD, NPAD,
        sLnd, (long)DH, (long)NL*NPAD, QS, 0.f, 0.f, nullptr, 0);
    softmax_wide<<<HEADS*NL, 256>>>(P.A3);
    zero_kernel<<<(HEADS*NL*DH + 255)/256, 256>>>(P.T, (long)HEADS*NL*DH);
    MMA_SM_SPK<<<grid64(NL, DH, HEADS*NSPLIT), 128>>>(
        P.A3, Vv, P.T, NL, DH, NPAD, NPAD, QKVD, DH,
        (long)NL*NPAD, (long)DH, sLnd, 1.f, 0.f, 0.f, nullptr, 0);
    MMA_SM_NN<<<grid64(NL, DH, HEADS), 128>>>(
        P.Z, P.T, P.U, NL, DH, NL, NL, DH, DH,
        sQ, sLnd, sLnd, 1.f, 0.f, 0.f, nullptr, 0);
    attn1_fused<<<dim3(NPAD/64, HEADS), 128, A1_SMEMB>>>(P.qkv, P.KL, P.U, P.attn);
    MMA_BIG_NN<<<grid128(NPAD, DIM, 1), 256>>>(
        P.attn, Wout, hio, NPAD, DIM, DIM, DIM, DIM, DIM,
        0, 0, 0, 1.f, 0.f, 0.f, bout, 2);
}

extern "C" void kernel_launch(void* const* d_in, const int* in_sizes, int n_in,
                              void* d_out, int out_size)
{
    const float* data      = (const float*)d_in[0];
    const float* W_fc1     = (const float*)d_in[1];
    const float* b_fc1     = (const float*)d_in[2];
    const float* cls_token = (const float*)d_in[3];
    const float* ln1_g     = (const float*)d_in[4];
    const float* ln1_b     = (const float*)d_in[5];
    const float* qkv1      = (const float*)d_in[6];
    const float* out1_w    = (const float*)d_in[7];
    const float* out1_b    = (const float*)d_in[8];
    const float* res1      = (const float*)d_in[9];
    const float* w7        = (const float*)d_in[10];
    const float* b7        = (const float*)d_in[11];
    const float* w5        = (const float*)d_in[12];
    const float* b5        = (const float*)d_in[13];
    const float* w3        = (const float*)d_in[14];
    const float* b3        = (const float*)d_in[15];
    const float* ln2_g     = (const float*)d_in[16];
    const float* ln2_b     = (const float*)d_in[17];
    const float* qkv2      = (const float*)d_in[18];
    const float* out2_w    = (const float*)d_in[19];
    const float* out2_b    = (const float*)d_in[20];
    const float* res2      = (const float*)d_in[21];
    const float* norm_g    = (const float*)d_in[22];
    const float* norm_b    = (const float*)d_in[23];
    const float* W_fc2     = (const float*)d_in[24];
    const float* b_fc2     = (const float*)d_in[25];

    Ptrs P;
    get_ptrs(P);

    cudaFuncSetAttribute(attn1_fused,
        cudaFuncAttributeMaxDynamicSharedMemorySize, A1_SMEMB);

    set_cls<<<1, DIM>>>(P.h, cls_token);
    MMA_BIG_NN<<<grid128(15000, DIM, 1), 256>>>(
        data, W_fc1, P.h + DIM, 15000, DIM, 1024, 1024, DIM, DIM,
        0, 0, 0, 1.f, 0.f, 0.f, b_fc1, 1);
    dup_rows<<<(129*DIM + 255)/256, 256>>>(P.h);

    // block 1 on h
    run_attention(P, P.h, ln1_g, ln1_b, qkv1, out1_w, out1_b, res1);

    // seed y's cls row with POST-block-1 token 0, then PPEG writes y+DIM
    copy_cls<<<1, DIM>>>(P.y, P.h);
    ppeg2<<<dim3((NPIX + PPP - 1)/PPP, DIM/128), 128>>>(
        P.h, P.y + DIM, w7, b7, w5, b5, w3, b3);

    // block 2 on y
    run_attention(P, P.y, ln2_g, ln2_b, qkv2, out2_w, out2_b, res2);

    final_head<<<1, DIM>>>(P.y, norm_g, norm_b, W_fc2, b_fc2, (float*)d_out, out_size);
}